// round 13
// baseline (speedup 1.0000x reference)
#include <cuda_runtime.h>
#include <cstdint>

// ---------------------------------------------------------------------------
// Problem constants
// ---------------------------------------------------------------------------
#define EMBD   2048
#define HEADS  8
#define HDIM   256
#define BATCH  2
#define SEQ    2048
#define BN_ROWS (BATCH*SEQ)      // 4096
#define QKV_N  (3*EMBD)          // 6144
#define NBH    (BATCH*HEADS)     // 16

// ---------------------------------------------------------------------------
// Device scratch — all GEMM operands stored PRE-SPLIT as packed bf16 hi/lo:
// word layout per K-pair: uint2{ hi(k),hi(k+1) , lo(k),lo(k+1) }.
// Row of K elements = K/2 uint2 = 4K bytes (same as fp32 row).
// ---------------------------------------------------------------------------
__device__ __align__(1024) uint2 g_px    [(size_t)BN_ROWS * EMBD / 2];   // x split      [4096][1024]
__device__ __align__(1024) uint2 g_pwqkvT[(size_t)QKV_N  * EMBD / 2];    // w_qkv^T split
__device__ __align__(1024) uint2 g_pwprojT[(size_t)EMBD  * EMBD / 2];    // w_proj^T split
__device__ __align__(1024) uint2 g_pq    [(size_t)NBH * SEQ  * HDIM / 2]; // Q split  [bh][n][d/2]
__device__ __align__(1024) uint2 g_pk    [(size_t)NBH * SEQ  * HDIM / 2]; // K split  [bh][n][d/2]
__device__ __align__(1024) uint2 g_pvT   [(size_t)NBH * HDIM * SEQ  / 2]; // V^T split[bh][d][n/2]
__device__ __align__(1024) float g_s     [(size_t)NBH * SEQ  * SEQ];      // logits fp32; softmax re-packs IN PLACE
__device__ __align__(1024) uint2 g_po    [(size_t)BN_ROWS * EMBD / 2];    // O split  [b*n][emb/2]

// ---------------------------------------------------------------------------
// Helpers
// ---------------------------------------------------------------------------
__device__ __forceinline__ void cp_async16(uint32_t s, const void* g) {
    asm volatile("cp.async.cg.shared.global [%0], [%1], 16;" :: "r"(s), "l"(g) : "memory");
}
#define CP_COMMIT() asm volatile("cp.async.commit_group;" ::: "memory")
#define CP_WAIT3()  asm volatile("cp.async.wait_group 3;" ::: "memory")

__device__ __forceinline__ uint32_t smem_u32(const void* p) {
    uint32_t a;
    asm("{ .reg .u64 t; cvta.to.shared.u64 t, %1; cvt.u32.u64 %0, t; }"
        : "=r"(a) : "l"(p));
    return a;
}

// Pack two floats to bf16x2 (word: lo16 = x0, hi16 = x1)
__device__ __forceinline__ uint32_t pack_bf16x2(float x0, float x1) {
    uint32_t w;
    asm("cvt.rn.bf16x2.f32 %0, %1, %2;" : "=r"(w) : "f"(x1), "f"(x0));
    return w;
}

// Split a float pair into bf16 hi-pair word + lo-pair word
__device__ __forceinline__ void split2(float x0, float x1, uint32_t& hw, uint32_t& lw) {
    hw = pack_bf16x2(x0, x1);
    float h0 = __uint_as_float(hw << 16);
    float h1 = __uint_as_float(hw & 0xffff0000u);
    lw = pack_bf16x2(x0 - h0, x1 - h1);
}

// Split a single float into bf16 hi/lo u16
__device__ __forceinline__ void split1(float v, unsigned short& hu, unsigned short& lu) {
    uint32_t hw = pack_bf16x2(v, 0.0f);
    float hf = __uint_as_float(hw << 16);
    uint32_t lw = pack_bf16x2(v - hf, 0.0f);
    hu = (unsigned short)(hw & 0xffffu);
    lu = (unsigned short)(lw & 0xffffu);
}

// bf16 tensor-core mma: D(16x8) += A(16x16) * B(16x8), A row-major, B col-major
__device__ __forceinline__ void mma_bf16(float* c, const uint32_t* a, const uint32_t* b) {
    asm volatile(
        "mma.sync.aligned.m16n8k16.row.col.f32.bf16.bf16.f32 "
        "{%0,%1,%2,%3}, {%4,%5,%6,%7}, {%8,%9}, {%0,%1,%2,%3};"
        : "+f"(c[0]), "+f"(c[1]), "+f"(c[2]), "+f"(c[3])
        : "r"(a[0]), "r"(a[1]), "r"(a[2]), "r"(a[3]), "r"(b[0]), "r"(b[1]));
}

// Load uint2 (hi-word, lo-word) from smem in one LDS.64
__device__ __forceinline__ void lds_v2(uint32_t addr, uint32_t& h, uint32_t& l) {
    asm volatile("ld.shared.v2.b32 {%0, %1}, [%2];" : "=r"(h), "=r"(l) : "r"(addr));
}

// ---------------------------------------------------------------------------
// bf16x3 HMMA GEMM: tile 128x128, BK=32 (2 x k16), 5-stage cp.async,
// 16 warps (4x4 grid, 32x32 warp tile), mma m16n8k16, operands pre-split.
// 512 threads => 4 warps/SMSP for latency hiding (was 2).
// MODE 0: x @ wqkvT^T     -> scatter split Q / K / V^T (+bias)
// MODE 1: Q @ K^T per bh  -> g_s (fp32)
// MODE 2: P @ V per bh    -> g_po (split, [b,n,h*d] layout)
// MODE 3: o @ wprojT^T    -> out (fp32, +bias)
// ---------------------------------------------------------------------------
#define SROWB   160                     // 128B data + 32B pad (bank-conflict-free LDS.64)
#define TILEB   (128 * SROWB)           // 20480 per operand per stage
#define STGB    (2 * TILEB)             // 40960
#define STAGES  5
#define SMEM_BYTES (STAGES * STGB)      // 204800
#define NTHREADS 512

template <int MODE>
__global__ __launch_bounds__(NTHREADS, 1)
void tc_gemm(const float* __restrict__ bias, float* __restrict__ Cout)
{
    constexpr int K     = (MODE == 1) ? HDIM : ((MODE == 2) ? SEQ : EMBD);
    constexpr int ITERS = K / 32;
    constexpr int ROWB  = K * 4;        // packed row bytes

    const int z  = blockIdx.z;
    const int m0 = blockIdx.y * 128;
    const int n0 = blockIdx.x * 128;

    const char* A; const char* B;
    if (MODE == 0)      { A = (const char*)g_px;
                          B = (const char*)g_pwqkvT; }
    else if (MODE == 1) { A = (const char*)(g_pq  + (size_t)z * SEQ * HDIM / 2);
                          B = (const char*)(g_pk  + (size_t)z * SEQ * HDIM / 2); }
    else if (MODE == 2) { A = (const char*)(g_s   + (size_t)z * SEQ * SEQ);     // packed in place
                          B = (const char*)(g_pvT + (size_t)z * HDIM * SEQ / 2); }
    else                { A = (const char*)g_po;
                          B = (const char*)g_pwprojT; }

    extern __shared__ __align__(128) char smem[];
    const uint32_t sb = smem_u32(smem);

    const int tid  = threadIdx.x;
    const int wid  = tid >> 5;
    const int lane = tid & 31;
    const int wm   = wid & 3;          // warp row (4)  -> 32 rows
    const int wn   = wid >> 2;         // warp col (4)  -> 32 cols
    const int grp  = lane >> 2;        // 0..7
    const int qid  = lane & 3;         // 0..3

    const char* Abase = A + (size_t)m0 * ROWB;
    const char* Bbase = B + (size_t)n0 * ROWB;

    auto issue = [&](int it, int s) {
        const uint32_t aS = sb + (uint32_t)s * STGB;
        const uint32_t bS = aS + TILEB;
        const char* gA = Abase + (size_t)it * 128;     // 32 elems = 16 uint2 = 128B
        const char* gB = Bbase + (size_t)it * 128;
        #pragma unroll
        for (int j = 0; j < 2; j++) {        // 1024 chunks / 512 thr = 2 each
            int u = tid + NTHREADS * j;
            int r = u >> 3, i = u & 7;
            cp_async16(aS + (uint32_t)(r * SROWB + i * 16), gA + (size_t)r * ROWB + i * 16);
        }
        #pragma unroll
        for (int j = 0; j < 2; j++) {
            int u = tid + NTHREADS * j;
            int r = u >> 3, i = u & 7;
            cp_async16(bS + (uint32_t)(r * SROWB + i * 16), gB + (size_t)r * ROWB + i * 16);
        }
        CP_COMMIT();
    };

    float acc[2][4][4];
    #pragma unroll
    for (int mt = 0; mt < 2; mt++)
        #pragma unroll
        for (int nt = 0; nt < 4; nt++)
            #pragma unroll
            for (int e = 0; e < 4; e++) acc[mt][nt][e] = 0.0f;

    issue(0, 0); issue(1, 1); issue(2, 2); issue(3, 3);

    int sc = 0;                 // stage being read this iter
    int si = 4 % STAGES;        // stage to fill next

    for (int it = 0; it < ITERS; it++) {
        CP_WAIT3();                 // stage 'it' group complete (<=3 pending)
        __syncthreads();            // also: all warps done reading stage 'si'

        if (it + 4 < ITERS) issue(it + 4, si);
        else                CP_COMMIT();   // keep group accounting uniform
        if (++si == STAGES) si = 0;

        const uint32_t aT = sb + (uint32_t)sc * STGB;
        const uint32_t bT = aT + TILEB;
        const uint32_t aW = aT + (uint32_t)(wm * 32 + grp) * SROWB + qid * 8;
        const uint32_t bW = bT + (uint32_t)(wn * 32 + grp) * SROWB + qid * 8;
        if (++sc == STAGES) sc = 0;

        #pragma unroll
        for (int ko = 0; ko < 2; ko++) {          // two k16 steps per BK=32
            const uint32_t koff = ko * 64;        // 8 pairs * 8B
            uint32_t ah[2][4], al[2][4];
            #pragma unroll
            for (int mt = 0; mt < 2; mt++) {
                const uint32_t p = aW + (uint32_t)(mt * 16) * SROWB + koff;
                lds_v2(p,                  ah[mt][0], al[mt][0]);   // (r,   q)
                lds_v2(p + 8 * SROWB,      ah[mt][1], al[mt][1]);   // (r+8, q)
                lds_v2(p + 32,             ah[mt][2], al[mt][2]);   // (r,   q+4)
                lds_v2(p + 8 * SROWB + 32, ah[mt][3], al[mt][3]);   // (r+8, q+4)
            }
            uint32_t bh[4][2], bl[4][2];
            #pragma unroll
            for (int nt = 0; nt < 4; nt++) {
                const uint32_t p = bW + (uint32_t)(nt * 8) * SROWB + koff;
                lds_v2(p,      bh[nt][0], bl[nt][0]);
                lds_v2(p + 32, bh[nt][1], bl[nt][1]);
            }
            // bf16x3: hi*hi + hi*lo + lo*hi (lo*lo dropped, ~2^-18)
            #pragma unroll
            for (int mt = 0; mt < 2; mt++)
                #pragma unroll
                for (int nt = 0; nt < 4; nt++) {
                    mma_bf16(acc[mt][nt], ah[mt], bh[nt]);
                    mma_bf16(acc[mt][nt], ah[mt], bl[nt]);
                    mma_bf16(acc[mt][nt], al[mt], bh[nt]);
                }
        }
        // no trailing barrier: next iter's top barrier orders stage reuse
    }

    // ---------------- epilogue ----------------
    #pragma unroll
    for (int mt = 0; mt < 2; mt++) {
        #pragma unroll
        for (int half = 0; half < 2; half++) {
            const int gi = m0 + wm * 32 + mt * 16 + grp + half * 8;
            if (MODE == 0) {
                // scatter split Q / K / V^T with bias
                const int bb = gi >> 11;            // batch
                const int ni = gi & (SEQ - 1);      // token
                #pragma unroll
                for (int nt = 0; nt < 4; nt++) {
                    #pragma unroll
                    for (int e = 0; e < 2; e++) {
                        const int gj = n0 + wn * 32 + nt * 8 + qid * 2 + e;
                        float val = acc[mt][nt][half * 2 + e] + bias[gj];
                        unsigned short hu, lu;
                        split1(val, hu, lu);
                        const int which = gj % 3;
                        const int tt    = gj / 3;
                        const int h     = tt >> 8;
                        const int d     = tt & (HDIM - 1);
                        const int bh    = (bb << 3) + h;
                        if (which == 2) {
                            unsigned short* vb = (unsigned short*)g_pvT;
                            size_t w = ((size_t)bh * HDIM + d) * (SEQ / 2) + (ni >> 1);
                            vb[w * 4 + (ni & 1)]     = hu;
                            vb[w * 4 + 2 + (ni & 1)] = lu;
                        } else {
                            unsigned short* qb = (unsigned short*)((which == 0) ? g_pq : g_pk);
                            size_t w = ((size_t)bh * SEQ + ni) * (HDIM / 2) + (d >> 1);
                            qb[w * 4 + (d & 1)]     = hu;
                            qb[w * 4 + 2 + (d & 1)] = lu;
                        }
                    }
                }
            } else if (MODE == 1) {
                // fp32 logits
                float* crow = g_s + (size_t)z * SEQ * SEQ
                            + (size_t)gi * SEQ + n0 + wn * 32 + qid * 2;
                #pragma unroll
                for (int nt = 0; nt < 4; nt++) {
                    float2 v;
                    v.x = acc[mt][nt][half * 2 + 0];
                    v.y = acc[mt][nt][half * 2 + 1];
                    *(float2*)(crow + nt * 8) = v;
                }
            } else if (MODE == 2) {
                // split O, [b*n][emb/2] packed
                const size_t orow = (size_t)(z >> 3) * SEQ + gi;
                #pragma unroll
                for (int nt = 0; nt < 4; nt++) {
                    const int ec = (z & 7) * HDIM + n0 + wn * 32 + nt * 8 + qid * 2;
                    uint32_t hw, lw;
                    split2(acc[mt][nt][half * 2 + 0], acc[mt][nt][half * 2 + 1], hw, lw);
                    g_po[orow * (EMBD / 2) + (ec >> 1)] = make_uint2(hw, lw);
                }
            } else {
                // fp32 output + bias
                float* crow = Cout + (size_t)gi * EMBD + n0 + wn * 32 + qid * 2;
                #pragma unroll
                for (int nt = 0; nt < 4; nt++) {
                    const int gj = n0 + wn * 32 + nt * 8 + qid * 2;
                    float2 v;
                    v.x = acc[mt][nt][half * 2 + 0] + bias[gj + 0];
                    v.y = acc[mt][nt][half * 2 + 1] + bias[gj + 1];
                    *(float2*)(crow + nt * 8) = v;
                }
            }
        }
    }
}

// ---------------------------------------------------------------------------
// Transpose + split weights: in fp32 [K][N] -> out packed [N][K/2]
// Input tile: rows 2*j0 .. 2*j0+63 (64 rows), cols n0 .. n0+31.
// Output tile: 32 cols (n) x 32 K-pairs (x) => 1024 uint2, 4 per thread.
// ---------------------------------------------------------------------------
__global__ __launch_bounds__(256)
void transpose_pack_k(const float* __restrict__ in, uint2* __restrict__ out,
                      int Kdim, int N)
{
    __shared__ float t[64][33];
    const int j0 = blockIdx.y * 32;     // output pair index base
    const int n0 = blockIdx.x * 32;
    const int x  = threadIdx.x & 31;
    const int y  = threadIdx.x >> 5;    // 0..7
    #pragma unroll
    for (int i = 0; i < 8; i++) {
        const int r = y + 8 * i;        // 0..63
        t[r][x] = in[(size_t)(2 * j0 + r) * N + n0 + x];
    }
    __syncthreads();
    #pragma unroll
    for (int i = 0; i < 4; i++) {       // 1024 outputs / 256 thr = 4
        const int n = y + 8 * i;        // 0..31
        uint32_t hw, lw;
        split2(t[2 * x][n], t[2 * x + 1][n], hw, lw);
        out[(size_t)(n0 + n) * (Kdim / 2) + j0 + x] = make_uint2(hw, lw);
    }
}

// Split-copy of x: fp32 pairs -> packed uint2
__global__ __launch_bounds__(256)
void splitx_k(const float2* __restrict__ in, uint2* __restrict__ out, int np)
{
    int i = blockIdx.x * blockDim.x + threadIdx.x;
    if (i < np) {
        float2 v = in[i];
        uint32_t hw, lw;
        split2(v.x, v.y, hw, lw);
        out[i] = make_uint2(hw, lw);
    }
}

// ---------------------------------------------------------------------------
// Row softmax over g_s, folds post-softmax 1/sqrt(EMB), re-packs the row
// IN PLACE as split bf16 pairs (for the P@V GEMM).
// ---------------------------------------------------------------------------
__global__ __launch_bounds__(256)
void softmax_k()
{
    constexpr float INV_SCALE = 0.02209708691207961f;   // 1/sqrt(2048)
    float* p = g_s + (size_t)blockIdx.x * SEQ;
    const int t = threadIdx.x, w = t >> 5, l = t & 31;

    float2 v[4];
    float m = -3.0e38f;
    #pragma unroll
    for (int u = 0; u < 4; u++) {
        v[u] = ((const float2*)p)[t + 256 * u];
        m = fmaxf(m, fmaxf(v[u].x, v[u].y));
    }
    #pragma unroll
    for (int o = 16; o > 0; o >>= 1) m = fmaxf(m, __shfl_xor_sync(~0u, m, o));

    __shared__ float redm[8], reds[8];
    if (l == 0) redm[w] = m;
    __syncthreads();
    m = redm[0];
    #pragma unroll
    for (int i = 1; i < 8; i++) m = fmaxf(m, redm[i]);

    float s = 0.0f;
    #pragma unroll
    for (int u = 0; u < 4; u++) {
        v[u].x = __expf(v[u].x - m);
        v[u].y = __expf(v[u].y - m);
        s += v[u].x + v[u].y;
    }
    #pragma unroll
    for (int o = 16; o > 0; o >>= 1) s += __shfl_xor_sync(~0u, s, o);
    if (l == 0) reds[w] = s;
    __syncthreads();
    s = reds[0];
    #pragma unroll
    for (int i = 1; i < 8; i++) s += reds[i];

    const float r = INV_SCALE / s;
    uint2* q = (uint2*)p;               // in-place re-pack (each word owned by one thread)
    #pragma unroll
    for (int u = 0; u < 4; u++) {
        uint32_t hw, lw;
        split2(v[u].x * r, v[u].y * r, hw, lw);
        q[t + 256 * u] = make_uint2(hw, lw);
    }
}

// ---------------------------------------------------------------------------
extern "C" void kernel_launch(void* const* d_in, const int* in_sizes, int n_in,
                              void* d_out, int out_size)
{
    const float* x      = (const float*)d_in[0];
    const float* w_qkv  = (const float*)d_in[1];
    const float* b_qkv  = (const float*)d_in[2];
    const float* w_proj = (const float*)d_in[3];
    const float* b_proj = (const float*)d_in[4];
    float*       out    = (float*)d_out;

    cudaFuncSetAttribute(tc_gemm<0>, cudaFuncAttributeMaxDynamicSharedMemorySize, SMEM_BYTES);
    cudaFuncSetAttribute(tc_gemm<1>, cudaFuncAttributeMaxDynamicSharedMemorySize, SMEM_BYTES);
    cudaFuncSetAttribute(tc_gemm<2>, cudaFuncAttributeMaxDynamicSharedMemorySize, SMEM_BYTES);
    cudaFuncSetAttribute(tc_gemm<3>, cudaFuncAttributeMaxDynamicSharedMemorySize, SMEM_BYTES);

    uint2* gpx; uint2* gwq; uint2* gwp;
    cudaGetSymbolAddress((void**)&gpx, g_px);
    cudaGetSymbolAddress((void**)&gwq, g_pwqkvT);
    cudaGetSymbolAddress((void**)&gwp, g_pwprojT);

    // 0) split x; transpose+split weights
    const int np = (BN_ROWS * EMBD) / 2;
    splitx_k<<<(np + 255) / 256, 256>>>((const float2*)x, gpx, np);
    transpose_pack_k<<<dim3(QKV_N / 32, EMBD / 64), 256>>>(w_qkv,  gwq, EMBD, QKV_N);
    transpose_pack_k<<<dim3(EMBD  / 32, EMBD / 64), 256>>>(w_proj, gwp, EMBD, EMBD);

    // 1) QKV projection + de-interleave into split Q / K / V^T
    tc_gemm<0><<<dim3(QKV_N / 128, BN_ROWS / 128, 1), NTHREADS, SMEM_BYTES>>>(b_qkv, nullptr);
    // 2) scores S = Q @ K^T per bh (fp32 out)
    tc_gemm<1><<<dim3(SEQ / 128, SEQ / 128, NBH), NTHREADS, SMEM_BYTES>>>(nullptr, nullptr);
    // 3) softmax (folds 1/sqrt(EMB)) + in-place split re-pack
    softmax_k<<<NBH * SEQ, 256>>>();
    // 4) O = P @ V per bh -> split [b, n, h*d]
    tc_gemm<2><<<dim3(HDIM / 128, SEQ / 128, NBH), NTHREADS, SMEM_BYTES>>>(nullptr, nullptr);
    // 5) final projection + bias (fp32 out)
    tc_gemm<3><<<dim3(EMBD / 128, BN_ROWS / 128, 1), NTHREADS, SMEM_BYTES>>>(b_proj, out);
}

// round 14
// speedup vs baseline: 1.0252x; 1.0252x over previous
#include <cuda_runtime.h>
#include <cstdint>

// ---------------------------------------------------------------------------
// Problem constants
// ---------------------------------------------------------------------------
#define EMBD   2048
#define HEADS  8
#define HDIM   256
#define BATCH  2
#define SEQ    2048
#define BN_ROWS (BATCH*SEQ)      // 4096
#define QKV_N  (3*EMBD)          // 6144
#define NBH    (BATCH*HEADS)     // 16

// ---------------------------------------------------------------------------
// Device scratch — all GEMM operands stored PRE-SPLIT as packed bf16 hi/lo:
// word layout per K-pair: uint2{ hi(k),hi(k+1) , lo(k),lo(k+1) }.
// Row of K elements = K/2 uint2 = 4K bytes (same as fp32 row).
// ---------------------------------------------------------------------------
__device__ __align__(1024) uint2 g_px    [(size_t)BN_ROWS * EMBD / 2];   // x split      [4096][1024]
__device__ __align__(1024) uint2 g_pwqkvT[(size_t)QKV_N  * EMBD / 2];    // w_qkv^T split
__device__ __align__(1024) uint2 g_pwprojT[(size_t)EMBD  * EMBD / 2];    // w_proj^T split
__device__ __align__(1024) uint2 g_pq    [(size_t)NBH * SEQ  * HDIM / 2]; // Q split  [bh][n][d/2]
__device__ __align__(1024) uint2 g_pk    [(size_t)NBH * SEQ  * HDIM / 2]; // K split  [bh][n][d/2]
__device__ __align__(1024) uint2 g_pvT   [(size_t)NBH * HDIM * SEQ  / 2]; // V^T split[bh][d][n/2]
__device__ __align__(1024) float g_s     [(size_t)NBH * SEQ  * SEQ];      // logits fp32; softmax re-packs IN PLACE
__device__ __align__(1024) uint2 g_po    [(size_t)BN_ROWS * EMBD / 2];    // O split  [b*n][emb/2]

// ---------------------------------------------------------------------------
// Helpers
// ---------------------------------------------------------------------------
__device__ __forceinline__ void cp_async16(uint32_t s, const void* g) {
    asm volatile("cp.async.cg.shared.global [%0], [%1], 16;" :: "r"(s), "l"(g) : "memory");
}
#define CP_COMMIT() asm volatile("cp.async.commit_group;" ::: "memory")
#define CP_WAIT1()  asm volatile("cp.async.wait_group 1;" ::: "memory")

__device__ __forceinline__ uint32_t smem_u32(const void* p) {
    uint32_t a;
    asm("{ .reg .u64 t; cvta.to.shared.u64 t, %1; cvt.u32.u64 %0, t; }"
        : "=r"(a) : "l"(p));
    return a;
}

// Pack two floats to bf16x2 (word: lo16 = x0, hi16 = x1)
__device__ __forceinline__ uint32_t pack_bf16x2(float x0, float x1) {
    uint32_t w;
    asm("cvt.rn.bf16x2.f32 %0, %1, %2;" : "=r"(w) : "f"(x1), "f"(x0));
    return w;
}

// Split a float pair into bf16 hi-pair word + lo-pair word
__device__ __forceinline__ void split2(float x0, float x1, uint32_t& hw, uint32_t& lw) {
    hw = pack_bf16x2(x0, x1);
    float h0 = __uint_as_float(hw << 16);
    float h1 = __uint_as_float(hw & 0xffff0000u);
    lw = pack_bf16x2(x0 - h0, x1 - h1);
}

// Split a single float into bf16 hi/lo u16
__device__ __forceinline__ void split1(float v, unsigned short& hu, unsigned short& lu) {
    uint32_t hw = pack_bf16x2(v, 0.0f);
    float hf = __uint_as_float(hw << 16);
    uint32_t lw = pack_bf16x2(v - hf, 0.0f);
    hu = (unsigned short)(hw & 0xffffu);
    lu = (unsigned short)(lw & 0xffffu);
}

// bf16 tensor-core mma: D(16x8) += A(16x16) * B(16x8), A row-major, B col-major
__device__ __forceinline__ void mma_bf16(float* c, const uint32_t* a, const uint32_t* b) {
    asm volatile(
        "mma.sync.aligned.m16n8k16.row.col.f32.bf16.bf16.f32 "
        "{%0,%1,%2,%3}, {%4,%5,%6,%7}, {%8,%9}, {%0,%1,%2,%3};"
        : "+f"(c[0]), "+f"(c[1]), "+f"(c[2]), "+f"(c[3])
        : "r"(a[0]), "r"(a[1]), "r"(a[2]), "r"(a[3]), "r"(b[0]), "r"(b[1]));
}

// Load uint2 (hi-word, lo-word) from smem in one LDS.64
__device__ __forceinline__ void lds_v2(uint32_t addr, uint32_t& h, uint32_t& l) {
    asm volatile("ld.shared.v2.b32 {%0, %1}, [%2];" : "=r"(h), "=r"(l) : "r"(addr));
}

// ---------------------------------------------------------------------------
// bf16x3 HMMA GEMM: CTA tile 128(M) x 256(N), BK=32 (2 x k16), 3-stage
// cp.async, 8 warps in 2x4, warp tile 64x64, mma m16n8k16, pre-split operands.
// Fatter warp tiles cut smem fragment traffic to 0.0208 B/FLOP (< crossbar
// balance 0.0313) so the tensor pipe, not the smem crossbar, binds.
// MODE 0: x @ wqkvT^T     -> scatter split Q / K / V^T (+bias)
// MODE 1: Q @ K^T per bh  -> g_s (fp32)
// MODE 2: P @ V per bh    -> g_po (split, [b,n,h*d] layout)
// MODE 3: o @ wprojT^T    -> out (fp32, +bias)
// ---------------------------------------------------------------------------
#define SROWB   160                     // 128B data + 32B pad (half-warp conflict-free LDS.64)
#define ATILEB  (128 * SROWB)           // 20480
#define BTILEB  (256 * SROWB)           // 40960
#define STGB    (ATILEB + BTILEB)       // 61440
#define STAGES  3
#define SMEM_BYTES (STAGES * STGB)      // 184320
#define NTHREADS 256

template <int MODE>
__global__ __launch_bounds__(NTHREADS, 1)
void tc_gemm(const float* __restrict__ bias, float* __restrict__ Cout)
{
    constexpr int K     = (MODE == 1) ? HDIM : ((MODE == 2) ? SEQ : EMBD);
    constexpr int ITERS = K / 32;
    constexpr int ROWB  = K * 4;        // packed row bytes

    const int z  = blockIdx.z;
    const int m0 = blockIdx.y * 128;
    const int n0 = blockIdx.x * 256;

    const char* A; const char* B;
    if (MODE == 0)      { A = (const char*)g_px;
                          B = (const char*)g_pwqkvT; }
    else if (MODE == 1) { A = (const char*)(g_pq  + (size_t)z * SEQ * HDIM / 2);
                          B = (const char*)(g_pk  + (size_t)z * SEQ * HDIM / 2); }
    else if (MODE == 2) { A = (const char*)(g_s   + (size_t)z * SEQ * SEQ);     // packed in place
                          B = (const char*)(g_pvT + (size_t)z * HDIM * SEQ / 2); }
    else                { A = (const char*)g_po;
                          B = (const char*)g_pwprojT; }

    extern __shared__ __align__(128) char smem[];
    const uint32_t sb = smem_u32(smem);

    const int tid  = threadIdx.x;
    const int wid  = tid >> 5;
    const int lane = tid & 31;
    const int wm   = wid & 1;          // warp row (2)  -> 64 rows
    const int wn   = wid >> 1;         // warp col (4)  -> 64 cols
    const int grp  = lane >> 2;        // 0..7
    const int qid  = lane & 3;         // 0..3

    const char* Abase = A + (size_t)m0 * ROWB;
    const char* Bbase = B + (size_t)n0 * ROWB;

    auto issue = [&](int it, int s) {
        const uint32_t aS = sb + (uint32_t)s * STGB;
        const uint32_t bS = aS + ATILEB;
        const char* gA = Abase + (size_t)it * 128;     // 32 elems = 16 uint2 = 128B
        const char* gB = Bbase + (size_t)it * 128;
        #pragma unroll
        for (int j = 0; j < 4; j++) {        // A: 1024 chunks / 256 thr = 4
            int u = tid + NTHREADS * j;
            int r = u >> 3, i = u & 7;
            cp_async16(aS + (uint32_t)(r * SROWB + i * 16), gA + (size_t)r * ROWB + i * 16);
        }
        #pragma unroll
        for (int j = 0; j < 8; j++) {        // B: 2048 chunks / 256 thr = 8
            int u = tid + NTHREADS * j;
            int r = u >> 3, i = u & 7;
            cp_async16(bS + (uint32_t)(r * SROWB + i * 16), gB + (size_t)r * ROWB + i * 16);
        }
        CP_COMMIT();
    };

    float acc[4][8][4];
    #pragma unroll
    for (int mt = 0; mt < 4; mt++)
        #pragma unroll
        for (int nt = 0; nt < 8; nt++)
            #pragma unroll
            for (int e = 0; e < 4; e++) acc[mt][nt][e] = 0.0f;

    issue(0, 0); issue(1, 1);

    int sc = 0;                 // stage being read this iter
    int si = 2;                 // stage to fill next

    for (int it = 0; it < ITERS; it++) {
        CP_WAIT1();                 // stage 'it' group complete (<=1 pending)
        __syncthreads();            // also: all warps done reading stage 'si'

        if (it + 2 < ITERS) issue(it + 2, si);
        else                CP_COMMIT();   // keep group accounting uniform
        if (++si == STAGES) si = 0;

        const uint32_t aT = sb + (uint32_t)sc * STGB;
        const uint32_t bT = aT + ATILEB;
        const uint32_t aW = aT + (uint32_t)(wm * 64 + grp) * SROWB + qid * 8;
        const uint32_t bW = bT + (uint32_t)(wn * 64 + grp) * SROWB + qid * 8;
        if (++sc == STAGES) sc = 0;

        #pragma unroll
        for (int ko = 0; ko < 2; ko++) {          // two k16 steps per BK=32
            const uint32_t koff = ko * 64;        // 8 pairs * 8B
            uint32_t ah[4][4], al[4][4];
            #pragma unroll
            for (int mt = 0; mt < 4; mt++) {
                const uint32_t p = aW + (uint32_t)(mt * 16) * SROWB + koff;
                lds_v2(p,                  ah[mt][0], al[mt][0]);   // (r,   q)
                lds_v2(p + 8 * SROWB,      ah[mt][1], al[mt][1]);   // (r+8, q)
                lds_v2(p + 32,             ah[mt][2], al[mt][2]);   // (r,   q+4)
                lds_v2(p + 8 * SROWB + 32, ah[mt][3], al[mt][3]);   // (r+8, q+4)
            }
            // B in two halves of 4 nt to cap live registers
            #pragma unroll
            for (int nh = 0; nh < 2; nh++) {
                uint32_t bh[4][2], bl[4][2];
                #pragma unroll
                for (int nt = 0; nt < 4; nt++) {
                    const uint32_t p = bW + (uint32_t)(nh * 32 + nt * 8) * SROWB + koff;
                    lds_v2(p,      bh[nt][0], bl[nt][0]);
                    lds_v2(p + 32, bh[nt][1], bl[nt][1]);
                }
                // bf16x3: hi*hi + hi*lo + lo*hi (lo*lo dropped, ~2^-18)
                #pragma unroll
                for (int mt = 0; mt < 4; mt++)
                    #pragma unroll
                    for (int nt = 0; nt < 4; nt++) {
                        float* c = acc[mt][nh * 4 + nt];
                        mma_bf16(c, ah[mt], bh[nt]);
                        mma_bf16(c, ah[mt], bl[nt]);
                        mma_bf16(c, al[mt], bh[nt]);
                    }
            }
        }
        // no trailing barrier: next iter's top barrier orders stage reuse
    }

    // ---------------- epilogue ----------------
    #pragma unroll
    for (int mt = 0; mt < 4; mt++) {
        #pragma unroll
        for (int half = 0; half < 2; half++) {
            const int gi = m0 + wm * 64 + mt * 16 + grp + half * 8;
            if (MODE == 0) {
                // scatter split Q / K / V^T with bias
                const int bb = gi >> 11;            // batch
                const int ni = gi & (SEQ - 1);      // token
                #pragma unroll
                for (int nt = 0; nt < 8; nt++) {
                    #pragma unroll
                    for (int e = 0; e < 2; e++) {
                        const int gj = n0 + wn * 64 + nt * 8 + qid * 2 + e;
                        float val = acc[mt][nt][half * 2 + e] + bias[gj];
                        unsigned short hu, lu;
                        split1(val, hu, lu);
                        const int which = gj % 3;
                        const int tt    = gj / 3;
                        const int h     = tt >> 8;
                        const int d     = tt & (HDIM - 1);
                        const int bh    = (bb << 3) + h;
                        if (which == 2) {
                            unsigned short* vb = (unsigned short*)g_pvT;
                            size_t w = ((size_t)bh * HDIM + d) * (SEQ / 2) + (ni >> 1);
                            vb[w * 4 + (ni & 1)]     = hu;
                            vb[w * 4 + 2 + (ni & 1)] = lu;
                        } else {
                            unsigned short* qb = (unsigned short*)((which == 0) ? g_pq : g_pk);
                            size_t w = ((size_t)bh * SEQ + ni) * (HDIM / 2) + (d >> 1);
                            qb[w * 4 + (d & 1)]     = hu;
                            qb[w * 4 + 2 + (d & 1)] = lu;
                        }
                    }
                }
            } else if (MODE == 1) {
                // fp32 logits
                float* crow = g_s + (size_t)z * SEQ * SEQ
                            + (size_t)gi * SEQ + n0 + wn * 64 + qid * 2;
                #pragma unroll
                for (int nt = 0; nt < 8; nt++) {
                    float2 v;
                    v.x = acc[mt][nt][half * 2 + 0];
                    v.y = acc[mt][nt][half * 2 + 1];
                    *(float2*)(crow + nt * 8) = v;
                }
            } else if (MODE == 2) {
                // split O, [b*n][emb/2] packed
                const size_t orow = (size_t)(z >> 3) * SEQ + gi;
                #pragma unroll
                for (int nt = 0; nt < 8; nt++) {
                    const int ec = (z & 7) * HDIM + n0 + wn * 64 + nt * 8 + qid * 2;
                    uint32_t hw, lw;
                    split2(acc[mt][nt][half * 2 + 0], acc[mt][nt][half * 2 + 1], hw, lw);
                    g_po[orow * (EMBD / 2) + (ec >> 1)] = make_uint2(hw, lw);
                }
            } else {
                // fp32 output + bias
                float* crow = Cout + (size_t)gi * EMBD + n0 + wn * 64 + qid * 2;
                #pragma unroll
                for (int nt = 0; nt < 8; nt++) {
                    const int gj = n0 + wn * 64 + nt * 8 + qid * 2;
                    float2 v;
                    v.x = acc[mt][nt][half * 2 + 0] + bias[gj + 0];
                    v.y = acc[mt][nt][half * 2 + 1] + bias[gj + 1];
                    *(float2*)(crow + nt * 8) = v;
                }
            }
        }
    }
}

// ---------------------------------------------------------------------------
// Transpose + split weights: in fp32 [K][N] -> out packed [N][K/2]
// Input tile: rows 2*j0 .. 2*j0+63 (64 rows), cols n0 .. n0+31.
// Output tile: 32 cols (n) x 32 K-pairs (x) => 1024 uint2, 4 per thread.
// ---------------------------------------------------------------------------
__global__ __launch_bounds__(256)
void transpose_pack_k(const float* __restrict__ in, uint2* __restrict__ out,
                      int Kdim, int N)
{
    __shared__ float t[64][33];
    const int j0 = blockIdx.y * 32;     // output pair index base
    const int n0 = blockIdx.x * 32;
    const int x  = threadIdx.x & 31;
    const int y  = threadIdx.x >> 5;    // 0..7
    #pragma unroll
    for (int i = 0; i < 8; i++) {
        const int r = y + 8 * i;        // 0..63
        t[r][x] = in[(size_t)(2 * j0 + r) * N + n0 + x];
    }
    __syncthreads();
    #pragma unroll
    for (int i = 0; i < 4; i++) {       // 1024 outputs / 256 thr = 4
        const int n = y + 8 * i;        // 0..31
        uint32_t hw, lw;
        split2(t[2 * x][n], t[2 * x + 1][n], hw, lw);
        out[(size_t)(n0 + n) * (Kdim / 2) + j0 + x] = make_uint2(hw, lw);
    }
}

// Split-copy of x: fp32 pairs -> packed uint2
__global__ __launch_bounds__(256)
void splitx_k(const float2* __restrict__ in, uint2* __restrict__ out, int np)
{
    int i = blockIdx.x * blockDim.x + threadIdx.x;
    if (i < np) {
        float2 v = in[i];
        uint32_t hw, lw;
        split2(v.x, v.y, hw, lw);
        out[i] = make_uint2(hw, lw);
    }
}

// ---------------------------------------------------------------------------
// Row softmax over g_s, folds post-softmax 1/sqrt(EMB), re-packs the row
// IN PLACE as split bf16 pairs (for the P@V GEMM).
// ---------------------------------------------------------------------------
__global__ __launch_bounds__(256)
void softmax_k()
{
    constexpr float INV_SCALE = 0.02209708691207961f;   // 1/sqrt(2048)
    float* p = g_s + (size_t)blockIdx.x * SEQ;
    const int t = threadIdx.x, w = t >> 5, l = t & 31;

    float2 v[4];
    float m = -3.0e38f;
    #pragma unroll
    for (int u = 0; u < 4; u++) {
        v[u] = ((const float2*)p)[t + 256 * u];
        m = fmaxf(m, fmaxf(v[u].x, v[u].y));
    }
    #pragma unroll
    for (int o = 16; o > 0; o >>= 1) m = fmaxf(m, __shfl_xor_sync(~0u, m, o));

    __shared__ float redm[8], reds[8];
    if (l == 0) redm[w] = m;
    __syncthreads();
    m = redm[0];
    #pragma unroll
    for (int i = 1; i < 8; i++) m = fmaxf(m, redm[i]);

    float s = 0.0f;
    #pragma unroll
    for (int u = 0; u < 4; u++) {
        v[u].x = __expf(v[u].x - m);
        v[u].y = __expf(v[u].y - m);
        s += v[u].x + v[u].y;
    }
    #pragma unroll
    for (int o = 16; o > 0; o >>= 1) s += __shfl_xor_sync(~0u, s, o);
    if (l == 0) reds[w] = s;
    __syncthreads();
    s = reds[0];
    #pragma unroll
    for (int i = 1; i < 8; i++) s += reds[i];

    const float r = INV_SCALE / s;
    uint2* q = (uint2*)p;               // in-place re-pack (each word owned by one thread)
    #pragma unroll
    for (int u = 0; u < 4; u++) {
        uint32_t hw, lw;
        split2(v[u].x * r, v[u].y * r, hw, lw);
        q[t + 256 * u] = make_uint2(hw, lw);
    }
}

// ---------------------------------------------------------------------------
extern "C" void kernel_launch(void* const* d_in, const int* in_sizes, int n_in,
                              void* d_out, int out_size)
{
    const float* x      = (const float*)d_in[0];
    const float* w_qkv  = (const float*)d_in[1];
    const float* b_qkv  = (const float*)d_in[2];
    const float* w_proj = (const float*)d_in[3];
    const float* b_proj = (const float*)d_in[4];
    float*       out    = (float*)d_out;

    cudaFuncSetAttribute(tc_gemm<0>, cudaFuncAttributeMaxDynamicSharedMemorySize, SMEM_BYTES);
    cudaFuncSetAttribute(tc_gemm<1>, cudaFuncAttributeMaxDynamicSharedMemorySize, SMEM_BYTES);
    cudaFuncSetAttribute(tc_gemm<2>, cudaFuncAttributeMaxDynamicSharedMemorySize, SMEM_BYTES);
    cudaFuncSetAttribute(tc_gemm<3>, cudaFuncAttributeMaxDynamicSharedMemorySize, SMEM_BYTES);

    uint2* gpx; uint2* gwq; uint2* gwp;
    cudaGetSymbolAddress((void**)&gpx, g_px);
    cudaGetSymbolAddress((void**)&gwq, g_pwqkvT);
    cudaGetSymbolAddress((void**)&gwp, g_pwprojT);

    // 0) split x; transpose+split weights
    const int np = (BN_ROWS * EMBD) / 2;
    splitx_k<<<(np + 255) / 256, 256>>>((const float2*)x, gpx, np);
    transpose_pack_k<<<dim3(QKV_N / 32, EMBD / 64), 256>>>(w_qkv,  gwq, EMBD, QKV_N);
    transpose_pack_k<<<dim3(EMBD  / 32, EMBD / 64), 256>>>(w_proj, gwp, EMBD, EMBD);

    // 1) QKV projection + de-interleave into split Q / K / V^T
    tc_gemm<0><<<dim3(QKV_N / 256, BN_ROWS / 128, 1), NTHREADS, SMEM_BYTES>>>(b_qkv, nullptr);
    // 2) scores S = Q @ K^T per bh (fp32 out)
    tc_gemm<1><<<dim3(SEQ / 256, SEQ / 128, NBH), NTHREADS, SMEM_BYTES>>>(nullptr, nullptr);
    // 3) softmax (folds 1/sqrt(EMB)) + in-place split re-pack
    softmax_k<<<NBH * SEQ, 256>>>();
    // 4) O = P @ V per bh -> split [b, n, h*d]
    tc_gemm<2><<<dim3(HDIM / 256, SEQ / 128, NBH), NTHREADS, SMEM_BYTES>>>(nullptr, nullptr);
    // 5) final projection + bias (fp32 out)
    tc_gemm<3><<<dim3(EMBD / 256, BN_ROWS / 128, 1), NTHREADS, SMEM_BYTES>>>(b_proj, out);
}

// round 15
// speedup vs baseline: 1.1027x; 1.0755x over previous
#include <cuda_runtime.h>
#include <cstdint>

// ---------------------------------------------------------------------------
// Problem constants
// ---------------------------------------------------------------------------
#define EMBD   2048
#define HEADS  8
#define HDIM   256
#define BATCH  2
#define SEQ    2048
#define BN_ROWS (BATCH*SEQ)      // 4096
#define QKV_N  (3*EMBD)          // 6144
#define NBH    (BATCH*HEADS)     // 16

// ---------------------------------------------------------------------------
// Tile geometry: CTA tile 128(M) x 256(N), K-chunk 32.
// Operands live in gmem EXACTLY in smem stage format: padded 160B rows,
// A tile = 128x160B = 20480B, B tile = 256x160B = 40960B, contiguous per
// (block, k-chunk). One cp.async.bulk per tile replaces ~1280 LDGSTS.
// Element format: bf16 hi/lo pairs, uint2{hi(k),hi(k+1), lo(k),lo(k+1)}.
// ---------------------------------------------------------------------------
#define SROWB   160
#define ATILEB  20480
#define BTILEB  40960
#define STGB    (ATILEB + BTILEB)       // 61440
#define STAGES  3
#define SMEM_BYTES (1024 + STAGES*STGB) // 185344
#define NTHREADS 256

// ---------------------------------------------------------------------------
// Device scratch (blocked-tile operand buffers + flat logits)
// ---------------------------------------------------------------------------
__device__ __align__(1024) unsigned char g_ax  [(size_t)32*64*ATILEB];      // x       A-tiles (mode0)
__device__ __align__(1024) unsigned char g_bqkv[(size_t)24*64*BTILEB];      // w_qkv^T B-tiles (mode0)
__device__ __align__(1024) unsigned char g_aq  [(size_t)16*16*8*ATILEB];    // Q       A-tiles (mode1, per bh)
__device__ __align__(1024) unsigned char g_bk  [(size_t)16*8*8*BTILEB];     // K       B-tiles (mode1, per bh)
__device__ __align__(1024) unsigned char g_ap  [(size_t)16*16*64*ATILEB];   // P       A-tiles (mode2, per bh)
__device__ __align__(1024) unsigned char g_bv  [(size_t)16*64*BTILEB];      // V^T     B-tiles (mode2, per bh)
__device__ __align__(1024) unsigned char g_ao  [(size_t)32*64*ATILEB];      // O       A-tiles (mode3)
__device__ __align__(1024) unsigned char g_bpr [(size_t)8*64*BTILEB];       // w_proj^T B-tiles (mode3)
__device__ __align__(1024) float g_s [(size_t)NBH*SEQ*SEQ];                 // logits fp32 (flat)

// ---------------------------------------------------------------------------
// Helpers
// ---------------------------------------------------------------------------
__device__ __forceinline__ uint32_t smem_u32(const void* p) {
    uint32_t a;
    asm("{ .reg .u64 t; cvta.to.shared.u64 t, %1; cvt.u32.u64 %0, t; }"
        : "=r"(a) : "l"(p));
    return a;
}

__device__ __forceinline__ uint32_t pack_bf16x2(float x0, float x1) {
    uint32_t w;
    asm("cvt.rn.bf16x2.f32 %0, %1, %2;" : "=r"(w) : "f"(x1), "f"(x0));
    return w;
}

__device__ __forceinline__ void split2(float x0, float x1, uint32_t& hw, uint32_t& lw) {
    hw = pack_bf16x2(x0, x1);
    float h0 = __uint_as_float(hw << 16);
    float h1 = __uint_as_float(hw & 0xffff0000u);
    lw = pack_bf16x2(x0 - h0, x1 - h1);
}

__device__ __forceinline__ void split1(float v, unsigned short& hu, unsigned short& lu) {
    uint32_t hw = pack_bf16x2(v, 0.0f);
    float hf = __uint_as_float(hw << 16);
    uint32_t lw = pack_bf16x2(v - hf, 0.0f);
    hu = (unsigned short)(hw & 0xffffu);
    lu = (unsigned short)(lw & 0xffffu);
}

__device__ __forceinline__ void mma_bf16(float* c, const uint32_t* a, const uint32_t* b) {
    asm volatile(
        "mma.sync.aligned.m16n8k16.row.col.f32.bf16.bf16.f32 "
        "{%0,%1,%2,%3}, {%4,%5,%6,%7}, {%8,%9}, {%0,%1,%2,%3};"
        : "+f"(c[0]), "+f"(c[1]), "+f"(c[2]), "+f"(c[3])
        : "r"(a[0]), "r"(a[1]), "r"(a[2]), "r"(a[3]), "r"(b[0]), "r"(b[1]));
}

__device__ __forceinline__ void lds_v2(uint32_t addr, uint32_t& h, uint32_t& l) {
    asm volatile("ld.shared.v2.b32 {%0, %1}, [%2];" : "=r"(h), "=r"(l) : "r"(addr));
}

// Bulk async copy gmem -> smem with mbarrier transaction completion (sm_90 base)
__device__ __forceinline__ void bulk_g2s(uint32_t s, const void* g, uint32_t bytes, uint32_t mb) {
    asm volatile(
        "cp.async.bulk.shared::cluster.global.mbarrier::complete_tx::bytes "
        "[%0], [%1], %2, [%3];"
        :: "r"(s), "l"(g), "r"(bytes), "r"(mb) : "memory");
}

#define MBAR_INIT(a, cnt) \
    asm volatile("mbarrier.init.shared.b64 [%0], %1;" :: "r"(a), "r"(cnt) : "memory")

#define MBAR_EXPECT_TX(a, bytes) \
    asm volatile("mbarrier.arrive.expect_tx.shared.b64 _, [%0], %1;" \
                 :: "r"(a), "r"((uint32_t)(bytes)) : "memory")

#define MBAR_WAIT(a, ph) do { \
    uint32_t _m = (a); uint32_t _p = (ph); uint32_t _d; \
    asm volatile("{\n\t.reg .pred p;\n\t" \
        "mbarrier.try_wait.parity.acquire.cta.shared::cta.b64 p, [%1], %2;\n\t" \
        "selp.b32 %0, 1, 0, p;\n\t}" : "=r"(_d) : "r"(_m), "r"(_p) : "memory"); \
    if (!_d) { \
        asm volatile("{\n\t.reg .pred P1;\n\t" \
            "WL_%=:\n\t" \
            "mbarrier.try_wait.parity.acquire.cta.shared::cta.b64 P1, [%0], %1, 0x989680;\n\t" \
            "@P1 bra.uni WD_%=;\n\t" \
            "bra.uni WL_%=;\n\t" \
            "WD_%=:\n\t}" :: "r"(_m), "r"(_p) : "memory"); \
    } } while (0)

// ---------------------------------------------------------------------------
// bf16x3 HMMA GEMM, operands pre-staged in blocked-tile gmem format.
// 8 warps (2x4), warp tile 64x64, mma m16n8k16, 3-stage bulk-copy pipeline.
// MODE 0: x @ wqkvT^T     -> scatter split Q / K / V^T tiles (+bias)
// MODE 1: Q @ K^T per bh  -> g_s (fp32 flat)
// MODE 2: P @ V per bh    -> O tiles ([b,n,h*d] order)
// MODE 3: o @ wprojT^T    -> out (fp32, +bias)
// ---------------------------------------------------------------------------
template <int MODE>
__global__ __launch_bounds__(NTHREADS, 1)
void tc_gemm(const float* __restrict__ bias, float* __restrict__ Cout)
{
    constexpr int KCH   = (MODE == 1) ? 8 : 64;   // k-chunks (K/32)
    constexpr int ITERS = KCH;

    const int z  = blockIdx.z;
    const int m0 = blockIdx.y * 128;
    const int n0 = blockIdx.x * 256;

    const unsigned char* Abase; const unsigned char* Bbase;
    if (MODE == 0)      { Abase = g_ax  + (size_t)blockIdx.y * 64 * ATILEB;
                          Bbase = g_bqkv + (size_t)blockIdx.x * 64 * BTILEB; }
    else if (MODE == 1) { Abase = g_aq + ((size_t)z * 16 + blockIdx.y) * 8 * ATILEB;
                          Bbase = g_bk + ((size_t)z * 8 + blockIdx.x) * 8 * BTILEB; }
    else if (MODE == 2) { Abase = g_ap + ((size_t)z * 16 + blockIdx.y) * 64 * ATILEB;
                          Bbase = g_bv + (size_t)z * 64 * BTILEB; }
    else                { Abase = g_ao  + (size_t)blockIdx.y * 64 * ATILEB;
                          Bbase = g_bpr + (size_t)blockIdx.x * 64 * BTILEB; }

    extern __shared__ __align__(128) char smem[];
    const uint32_t sb = smem_u32(smem);

    const int tid  = threadIdx.x;
    const int wid  = tid >> 5;
    const int lane = tid & 31;
    const int wm   = wid & 1;          // warp row (2)  -> 64 rows
    const int wn   = wid >> 1;         // warp col (4)  -> 64 cols
    const int grp  = lane >> 2;        // 0..7
    const int qid  = lane & 3;         // 0..3

    // mbarriers in header
    if (tid == 0) {
        #pragma unroll
        for (int s = 0; s < STAGES; s++) MBAR_INIT(sb + 16 * s, 1);
    }
    __syncthreads();

    auto issue = [&](int it, int s) {
        if (tid == 0) {
            const uint32_t mb = sb + 16 * s;
            const uint32_t dA = sb + 1024 + (uint32_t)s * STGB;
            MBAR_EXPECT_TX(mb, STGB);
            bulk_g2s(dA, Abase + (size_t)it * ATILEB, ATILEB, mb);
            bulk_g2s(dA + ATILEB, Bbase + (size_t)it * BTILEB, 20480, mb);
            bulk_g2s(dA + ATILEB + 20480, Bbase + (size_t)it * BTILEB + 20480, 20480, mb);
        }
    };

    float acc[4][8][4];
    #pragma unroll
    for (int mt = 0; mt < 4; mt++)
        #pragma unroll
        for (int nt = 0; nt < 8; nt++)
            #pragma unroll
            for (int e = 0; e < 4; e++) acc[mt][nt][e] = 0.0f;

    issue(0, 0);
    issue(1, 1);

    for (int it = 0; it < ITERS; it++) {
        const int s = it % STAGES;
        __syncthreads();            // all warps done reading stage (it+2)%3 (used at it-1)

        if (it + 2 < ITERS) issue(it + 2, (it + 2) % STAGES);

        MBAR_WAIT(sb + 16 * s, (it / STAGES) & 1);   // stage 'it' data resident

        const uint32_t aT = sb + 1024 + (uint32_t)s * STGB;
        const uint32_t bT = aT + ATILEB;
        const uint32_t aW = aT + (uint32_t)(wm * 64 + grp) * SROWB + qid * 8;
        const uint32_t bW = bT + (uint32_t)(wn * 64 + grp) * SROWB + qid * 8;

        #pragma unroll
        for (int ko = 0; ko < 2; ko++) {          // two k16 steps per chunk
            const uint32_t koff = ko * 64;        // 8 pairs * 8B
            uint32_t ah[4][4], al[4][4];
            #pragma unroll
            for (int mt = 0; mt < 4; mt++) {
                const uint32_t p = aW + (uint32_t)(mt * 16) * SROWB + koff;
                lds_v2(p,                  ah[mt][0], al[mt][0]);   // (r,   q)
                lds_v2(p + 8 * SROWB,      ah[mt][1], al[mt][1]);   // (r+8, q)
                lds_v2(p + 32,             ah[mt][2], al[mt][2]);   // (r,   q+4)
                lds_v2(p + 8 * SROWB + 32, ah[mt][3], al[mt][3]);   // (r+8, q+4)
            }
            // B in two halves of 4 nt to cap live registers
            #pragma unroll
            for (int nh = 0; nh < 2; nh++) {
                uint32_t bh[4][2], bl[4][2];
                #pragma unroll
                for (int nt = 0; nt < 4; nt++) {
                    const uint32_t p = bW + (uint32_t)(nh * 32 + nt * 8) * SROWB + koff;
                    lds_v2(p,      bh[nt][0], bl[nt][0]);
                    lds_v2(p + 32, bh[nt][1], bl[nt][1]);
                }
                // bf16x3: hi*hi + hi*lo + lo*hi (lo*lo dropped, ~2^-18)
                #pragma unroll
                for (int mt = 0; mt < 4; mt++)
                    #pragma unroll
                    for (int nt = 0; nt < 4; nt++) {
                        float* c = acc[mt][nh * 4 + nt];
                        mma_bf16(c, ah[mt], bh[nt]);
                        mma_bf16(c, ah[mt], bl[nt]);
                        mma_bf16(c, al[mt], bh[nt]);
                    }
            }
        }
    }

    // ---------------- epilogue ----------------
    #pragma unroll
    for (int mt = 0; mt < 4; mt++) {
        #pragma unroll
        for (int half = 0; half < 2; half++) {
            const int gi = m0 + wm * 64 + mt * 16 + grp + half * 8;
            if (MODE == 0) {
                // scatter split Q / K / V^T into blocked tiles, with bias
                const int bb = gi >> 11;            // batch
                const int ni = gi & (SEQ - 1);      // token
                #pragma unroll
                for (int nt = 0; nt < 8; nt++) {
                    #pragma unroll
                    for (int e = 0; e < 2; e++) {
                        const int gj = n0 + wn * 64 + nt * 8 + qid * 2 + e;
                        float val = acc[mt][nt][half * 2 + e] + bias[gj];
                        unsigned short hu, lu;
                        split1(val, hu, lu);
                        const int which = gj % 3;
                        const int tt    = gj / 3;
                        const int h     = tt >> 8;
                        const int d     = tt & (HDIM - 1);
                        const int bh    = (bb << 3) + h;
                        if (which == 0) {
                            const int p = d >> 1, sl = d & 1;
                            unsigned short* w = (unsigned short*)(g_aq
                                + (size_t)bh * (16 * 8 * ATILEB)
                                + ((size_t)((ni >> 7) * 8 + (p >> 4)) * 128 + (ni & 127)) * SROWB
                                + (p & 15) * 8);
                            w[sl] = hu; w[2 + sl] = lu;
                        } else if (which == 1) {
                            const int p = d >> 1, sl = d & 1;
                            unsigned short* w = (unsigned short*)(g_bk
                                + (size_t)bh * (8 * 8 * BTILEB)
                                + ((size_t)((ni >> 8) * 8 + (p >> 4)) * 256 + (ni & 255)) * SROWB
                                + (p & 15) * 8);
                            w[sl] = hu; w[2 + sl] = lu;
                        } else {
                            const int p = ni >> 1, sl = ni & 1;
                            unsigned short* w = (unsigned short*)(g_bv
                                + (size_t)bh * (64 * BTILEB)
                                + ((size_t)(p >> 4) * 256 + d) * SROWB
                                + (p & 15) * 8);
                            w[sl] = hu; w[2 + sl] = lu;
                        }
                    }
                }
            } else if (MODE == 1) {
                // fp32 logits (flat)
                float* crow = g_s + (size_t)z * SEQ * SEQ
                            + (size_t)gi * SEQ + n0 + wn * 64 + qid * 2;
                #pragma unroll
                for (int nt = 0; nt < 8; nt++) {
                    float2 v;
                    v.x = acc[mt][nt][half * 2 + 0];
                    v.y = acc[mt][nt][half * 2 + 1];
                    *(float2*)(crow + nt * 8) = v;
                }
            } else if (MODE == 2) {
                // split O into blocked A-tiles for mode3
                const int orow = (z >> 3) * SEQ + gi;
                #pragma unroll
                for (int nt = 0; nt < 8; nt++) {
                    const int ec = (z & 7) * HDIM + n0 + wn * 64 + nt * 8 + qid * 2;
                    const int p = ec >> 1;
                    uint32_t hw, lw;
                    split2(acc[mt][nt][half * 2 + 0], acc[mt][nt][half * 2 + 1], hw, lw);
                    *(uint2*)(g_ao
                        + ((size_t)((orow >> 7) * 64 + (p >> 4)) * 128 + (orow & 127)) * SROWB
                        + (p & 15) * 8) = make_uint2(hw, lw);
                }
            } else {
                // fp32 output + bias
                float* crow = Cout + (size_t)gi * EMBD + n0 + wn * 64 + qid * 2;
                #pragma unroll
                for (int nt = 0; nt < 8; nt++) {
                    const int gj = n0 + wn * 64 + nt * 8 + qid * 2;
                    float2 v;
                    v.x = acc[mt][nt][half * 2 + 0] + bias[gj + 0];
                    v.y = acc[mt][nt][half * 2 + 1] + bias[gj + 1];
                    *(float2*)(crow + nt * 8) = v;
                }
            }
        }
    }
}

// ---------------------------------------------------------------------------
// Transpose + split weights: fp32 [K][N] -> blocked B-tiles (Tn=256, KCH=64)
// ---------------------------------------------------------------------------
__global__ __launch_bounds__(256)
void transpose_pack_k(const float* __restrict__ in, unsigned char* __restrict__ out,
                      int N)
{
    __shared__ float t[64][33];
    const int j0 = blockIdx.y * 32;     // output pair index base
    const int n0 = blockIdx.x * 32;
    const int x  = threadIdx.x & 31;
    const int y  = threadIdx.x >> 5;    // 0..7
    #pragma unroll
    for (int i = 0; i < 8; i++) {
        const int r = y + 8 * i;        // 0..63
        t[r][x] = in[(size_t)(2 * j0 + r) * N + n0 + x];
    }
    __syncthreads();
    #pragma unroll
    for (int i = 0; i < 4; i++) {
        const int n  = n0 + y + 8 * i;
        const int jp = j0 + x;
        uint32_t hw, lw;
        split2(t[2 * x][y + 8 * i], t[2 * x + 1][y + 8 * i], hw, lw);
        *(uint2*)(out
            + ((size_t)((n >> 8) * 64 + (jp >> 4)) * 256 + (n & 255)) * SROWB
            + (jp & 15) * 8) = make_uint2(hw, lw);
    }
}

// Split-copy of x into blocked A-tiles (Tm=128, KCH=64)
__global__ __launch_bounds__(256)
void splitx_k(const float2* __restrict__ in)
{
    const int i = blockIdx.x * blockDim.x + threadIdx.x;
    if (i < BN_ROWS * (EMBD / 2)) {
        const int m = i >> 10;          // row (EMBD/2 = 1024 pairs per row)
        const int p = i & 1023;         // pair index
        float2 v = in[i];
        uint32_t hw, lw;
        split2(v.x, v.y, hw, lw);
        *(uint2*)(g_ax
            + ((size_t)((m >> 7) * 64 + (p >> 4)) * 128 + (m & 127)) * SROWB
            + (p & 15) * 8) = make_uint2(hw, lw);
    }
}

// ---------------------------------------------------------------------------
// Row softmax over flat g_s, folds 1/sqrt(EMB), writes split P into blocked
// A-tiles for the P@V GEMM (Tm=128, KCH=64, per bh).
// ---------------------------------------------------------------------------
__global__ __launch_bounds__(256)
void softmax_k()
{
    constexpr float INV_SCALE = 0.02209708691207961f;   // 1/sqrt(2048)
    const int bh = blockIdx.x >> 11;
    const int q  = blockIdx.x & 2047;
    const float* p = g_s + (size_t)blockIdx.x * SEQ;
    const int t = threadIdx.x, w = t >> 5, l = t & 31;

    float2 v[4];
    float m = -3.0e38f;
    #pragma unroll
    for (int u = 0; u < 4; u++) {
        v[u] = ((const float2*)p)[t + 256 * u];
        m = fmaxf(m, fmaxf(v[u].x, v[u].y));
    }
    #pragma unroll
    for (int o = 16; o > 0; o >>= 1) m = fmaxf(m, __shfl_xor_sync(~0u, m, o));

    __shared__ float redm[8], reds[8];
    if (l == 0) redm[w] = m;
    __syncthreads();
    m = redm[0];
    #pragma unroll
    for (int i = 1; i < 8; i++) m = fmaxf(m, redm[i]);

    float s = 0.0f;
    #pragma unroll
    for (int u = 0; u < 4; u++) {
        v[u].x = __expf(v[u].x - m);
        v[u].y = __expf(v[u].y - m);
        s += v[u].x + v[u].y;
    }
    #pragma unroll
    for (int o = 16; o > 0; o >>= 1) s += __shfl_xor_sync(~0u, s, o);
    if (l == 0) reds[w] = s;
    __syncthreads();
    s = reds[0];
    #pragma unroll
    for (int i = 1; i < 8; i++) s += reds[i];

    const float r = INV_SCALE / s;
    unsigned char* obase = g_ap + (size_t)bh * (16 * 64 * ATILEB)
                         + (size_t)(q >> 7) * (64 * ATILEB)
                         + (size_t)(q & 127) * SROWB;
    #pragma unroll
    for (int u = 0; u < 4; u++) {
        const int kp = t + 256 * u;     // pair index over SEQ/2
        uint32_t hw, lw;
        split2(v[u].x * r, v[u].y * r, hw, lw);
        *(uint2*)(obase + (size_t)(kp >> 4) * ATILEB + (kp & 15) * 8) = make_uint2(hw, lw);
    }
}

// ---------------------------------------------------------------------------
extern "C" void kernel_launch(void* const* d_in, const int* in_sizes, int n_in,
                              void* d_out, int out_size)
{
    const float* x      = (const float*)d_in[0];
    const float* w_qkv  = (const float*)d_in[1];
    const float* b_qkv  = (const float*)d_in[2];
    const float* w_proj = (const float*)d_in[3];
    const float* b_proj = (const float*)d_in[4];
    float*       out    = (float*)d_out;

    cudaFuncSetAttribute(tc_gemm<0>, cudaFuncAttributeMaxDynamicSharedMemorySize, SMEM_BYTES);
    cudaFuncSetAttribute(tc_gemm<1>, cudaFuncAttributeMaxDynamicSharedMemorySize, SMEM_BYTES);
    cudaFuncSetAttribute(tc_gemm<2>, cudaFuncAttributeMaxDynamicSharedMemorySize, SMEM_BYTES);
    cudaFuncSetAttribute(tc_gemm<3>, cudaFuncAttributeMaxDynamicSharedMemorySize, SMEM_BYTES);

    unsigned char* gwq; unsigned char* gwp;
    cudaGetSymbolAddress((void**)&gwq, g_bqkv);
    cudaGetSymbolAddress((void**)&gwp, g_bpr);

    // 0) split x into A-tiles; transpose+split weights into B-tiles
    const int np = BN_ROWS * (EMBD / 2);
    splitx_k<<<(np + 255) / 256, 256>>>((const float2*)x);
    transpose_pack_k<<<dim3(QKV_N / 32, EMBD / 64), 256>>>(w_qkv,  gwq, QKV_N);
    transpose_pack_k<<<dim3(EMBD  / 32, EMBD / 64), 256>>>(w_proj, gwp, EMBD);

    // 1) QKV projection + de-interleave into split Q / K / V^T tiles
    tc_gemm<0><<<dim3(QKV_N / 256, BN_ROWS / 128, 1), NTHREADS, SMEM_BYTES>>>(b_qkv, nullptr);
    // 2) scores S = Q @ K^T per bh (fp32 flat out)
    tc_gemm<1><<<dim3(SEQ / 256, SEQ / 128, NBH), NTHREADS, SMEM_BYTES>>>(nullptr, nullptr);
    // 3) softmax (folds 1/sqrt(EMB)) -> split P tiles
    softmax_k<<<NBH * SEQ, 256>>>();
    // 4) O = P @ V per bh -> split O tiles ([b, n, h*d] order)
    tc_gemm<2><<<dim3(HDIM / 256, SEQ / 128, NBH), NTHREADS, SMEM_BYTES>>>(nullptr, nullptr);
    // 5) final projection + bias (fp32 out)
    tc_gemm<3><<<dim3(EMBD / 256, BN_ROWS / 128, 1), NTHREADS, SMEM_BYTES>>>(b_proj, out);
}

// round 16
// speedup vs baseline: 1.1071x; 1.0041x over previous
#include <cuda_runtime.h>
#include <cstdint>

// ---------------------------------------------------------------------------
// Problem constants
// ---------------------------------------------------------------------------
#define EMBD   2048
#define HEADS  8
#define HDIM   256
#define BATCH  2
#define SEQ    2048
#define BN_ROWS (BATCH*SEQ)      // 4096
#define QKV_N  (3*EMBD)          // 6144
#define NBH    (BATCH*HEADS)     // 16

// ---------------------------------------------------------------------------
// Tile geometry: CTA tile 128(M) x 256(N), K-chunk 32.
// Operands live in gmem EXACTLY in smem stage format: padded 160B rows,
// A tile = 128x160B = 20480B, B tile = 256x160B = 40960B, contiguous per
// (block, k-chunk). One cp.async.bulk per tile replaces ~1280 LDGSTS.
// Element format: bf16 hi/lo pairs, uint2{hi(k),hi(k+1), lo(k),lo(k+1)}.
// ---------------------------------------------------------------------------
#define SROWB   160
#define ATILEB  20480
#define BTILEB  40960
#define STGB    (ATILEB + BTILEB)       // 61440
#define STAGES  3
#define SMEM_BYTES (1024 + STAGES*STGB) // 185344
#define NTHREADS 256

// ---------------------------------------------------------------------------
// Device scratch (blocked-tile operand buffers + flat logits)
// ---------------------------------------------------------------------------
__device__ __align__(1024) unsigned char g_ax  [(size_t)32*64*ATILEB];      // x       A-tiles (mode0)
__device__ __align__(1024) unsigned char g_bqkv[(size_t)24*64*BTILEB];      // w_qkv^T B-tiles (mode0)
__device__ __align__(1024) unsigned char g_aq  [(size_t)16*16*8*ATILEB];    // Q       A-tiles (mode1, per bh)
__device__ __align__(1024) unsigned char g_bk  [(size_t)16*8*8*BTILEB];     // K       B-tiles (mode1, per bh)
__device__ __align__(1024) unsigned char g_ap  [(size_t)16*16*64*ATILEB];   // P       A-tiles (mode2, per bh)
__device__ __align__(1024) unsigned char g_bv  [(size_t)16*64*BTILEB];      // V^T     B-tiles (mode2, per bh)
__device__ __align__(1024) unsigned char g_ao  [(size_t)32*64*ATILEB];      // O       A-tiles (mode3)
__device__ __align__(1024) unsigned char g_bpr [(size_t)8*64*BTILEB];       // w_proj^T B-tiles (mode3)
__device__ __align__(1024) float g_s [(size_t)NBH*SEQ*SEQ];                 // logits fp32 (flat)

// ---------------------------------------------------------------------------
// Helpers
// ---------------------------------------------------------------------------
__device__ __forceinline__ uint32_t smem_u32(const void* p) {
    uint32_t a;
    asm("{ .reg .u64 t; cvta.to.shared.u64 t, %1; cvt.u32.u64 %0, t; }"
        : "=r"(a) : "l"(p));
    return a;
}

__device__ __forceinline__ uint32_t pack_bf16x2(float x0, float x1) {
    uint32_t w;
    asm("cvt.rn.bf16x2.f32 %0, %1, %2;" : "=r"(w) : "f"(x1), "f"(x0));
    return w;
}

__device__ __forceinline__ void split2(float x0, float x1, uint32_t& hw, uint32_t& lw) {
    hw = pack_bf16x2(x0, x1);
    float h0 = __uint_as_float(hw << 16);
    float h1 = __uint_as_float(hw & 0xffff0000u);
    lw = pack_bf16x2(x0 - h0, x1 - h1);
}

__device__ __forceinline__ void split1(float v, unsigned short& hu, unsigned short& lu) {
    uint32_t hw = pack_bf16x2(v, 0.0f);
    float hf = __uint_as_float(hw << 16);
    uint32_t lw = pack_bf16x2(v - hf, 0.0f);
    hu = (unsigned short)(hw & 0xffffu);
    lu = (unsigned short)(lw & 0xffffu);
}

__device__ __forceinline__ void mma_bf16(float* c, const uint32_t* a, const uint32_t* b) {
    asm volatile(
        "mma.sync.aligned.m16n8k16.row.col.f32.bf16.bf16.f32 "
        "{%0,%1,%2,%3}, {%4,%5,%6,%7}, {%8,%9}, {%0,%1,%2,%3};"
        : "+f"(c[0]), "+f"(c[1]), "+f"(c[2]), "+f"(c[3])
        : "r"(a[0]), "r"(a[1]), "r"(a[2]), "r"(a[3]), "r"(b[0]), "r"(b[1]));
}

__device__ __forceinline__ void lds_v2(uint32_t addr, uint32_t& h, uint32_t& l) {
    asm volatile("ld.shared.v2.b32 {%0, %1}, [%2];" : "=r"(h), "=r"(l) : "r"(addr));
}

// Bulk async copy gmem -> smem with mbarrier transaction completion (sm_90 base)
__device__ __forceinline__ void bulk_g2s(uint32_t s, const void* g, uint32_t bytes, uint32_t mb) {
    asm volatile(
        "cp.async.bulk.shared::cluster.global.mbarrier::complete_tx::bytes "
        "[%0], [%1], %2, [%3];"
        :: "r"(s), "l"(g), "r"(bytes), "r"(mb) : "memory");
}

#define MBAR_INIT(a, cnt) \
    asm volatile("mbarrier.init.shared.b64 [%0], %1;" :: "r"(a), "r"(cnt) : "memory")

#define MBAR_EXPECT_TX(a, bytes) \
    asm volatile("mbarrier.arrive.expect_tx.shared.b64 _, [%0], %1;" \
                 :: "r"(a), "r"((uint32_t)(bytes)) : "memory")

#define MBAR_WAIT(a, ph) do { \
    uint32_t _m = (a); uint32_t _p = (ph); uint32_t _d; \
    asm volatile("{\n\t.reg .pred p;\n\t" \
        "mbarrier.try_wait.parity.acquire.cta.shared::cta.b64 p, [%1], %2;\n\t" \
        "selp.b32 %0, 1, 0, p;\n\t}" : "=r"(_d) : "r"(_m), "r"(_p) : "memory"); \
    if (!_d) { \
        asm volatile("{\n\t.reg .pred P1;\n\t" \
            "WL_%=:\n\t" \
            "mbarrier.try_wait.parity.acquire.cta.shared::cta.b64 P1, [%0], %1, 0x989680;\n\t" \
            "@P1 bra.uni WD_%=;\n\t" \
            "bra.uni WL_%=;\n\t" \
            "WD_%=:\n\t}" :: "r"(_m), "r"(_p) : "memory"); \
    } } while (0)

// ---------------------------------------------------------------------------
// bf16x3 HMMA GEMM, operands pre-staged in blocked-tile gmem format.
// 8 warps (2x4), warp tile 64x64, mma m16n8k16, 3-stage bulk-copy pipeline.
// TERM-MAJOR MMA ordering: consecutive MMAs hit different accumulators so
// the HMMA stream issues at reciprocal throughput, not accumulator latency.
// MODE 0: x @ wqkvT^T     -> scatter split Q / K / V^T tiles (+bias)
// MODE 1: Q @ K^T per bh  -> g_s (fp32 flat)
// MODE 2: P @ V per bh    -> O tiles ([b,n,h*d] order)
// MODE 3: o @ wprojT^T    -> out (fp32, +bias)
// ---------------------------------------------------------------------------
template <int MODE>
__global__ __launch_bounds__(NTHREADS, 1)
void tc_gemm(const float* __restrict__ bias, float* __restrict__ Cout)
{
    constexpr int KCH   = (MODE == 1) ? 8 : 64;   // k-chunks (K/32)
    constexpr int ITERS = KCH;

    const int z  = blockIdx.z;
    const int m0 = blockIdx.y * 128;
    const int n0 = blockIdx.x * 256;

    const unsigned char* Abase; const unsigned char* Bbase;
    if (MODE == 0)      { Abase = g_ax  + (size_t)blockIdx.y * 64 * ATILEB;
                          Bbase = g_bqkv + (size_t)blockIdx.x * 64 * BTILEB; }
    else if (MODE == 1) { Abase = g_aq + ((size_t)z * 16 + blockIdx.y) * 8 * ATILEB;
                          Bbase = g_bk + ((size_t)z * 8 + blockIdx.x) * 8 * BTILEB; }
    else if (MODE == 2) { Abase = g_ap + ((size_t)z * 16 + blockIdx.y) * 64 * ATILEB;
                          Bbase = g_bv + (size_t)z * 64 * BTILEB; }
    else                { Abase = g_ao  + (size_t)blockIdx.y * 64 * ATILEB;
                          Bbase = g_bpr + (size_t)blockIdx.x * 64 * BTILEB; }

    extern __shared__ __align__(128) char smem[];
    const uint32_t sb = smem_u32(smem);

    const int tid  = threadIdx.x;
    const int wid  = tid >> 5;
    const int lane = tid & 31;
    const int wm   = wid & 1;          // warp row (2)  -> 64 rows
    const int wn   = wid >> 1;         // warp col (4)  -> 64 cols
    const int grp  = lane >> 2;        // 0..7
    const int qid  = lane & 3;         // 0..3

    // mbarriers in header
    if (tid == 0) {
        #pragma unroll
        for (int s = 0; s < STAGES; s++) MBAR_INIT(sb + 16 * s, 1);
    }
    __syncthreads();

    auto issue = [&](int it, int s) {
        if (tid == 0) {
            const uint32_t mb = sb + 16 * s;
            const uint32_t dA = sb + 1024 + (uint32_t)s * STGB;
            MBAR_EXPECT_TX(mb, STGB);
            bulk_g2s(dA, Abase + (size_t)it * ATILEB, ATILEB, mb);
            bulk_g2s(dA + ATILEB, Bbase + (size_t)it * BTILEB, 20480, mb);
            bulk_g2s(dA + ATILEB + 20480, Bbase + (size_t)it * BTILEB + 20480, 20480, mb);
        }
    };

    float acc[4][8][4];
    #pragma unroll
    for (int mt = 0; mt < 4; mt++)
        #pragma unroll
        for (int nt = 0; nt < 8; nt++)
            #pragma unroll
            for (int e = 0; e < 4; e++) acc[mt][nt][e] = 0.0f;

    issue(0, 0);
    issue(1, 1);

    for (int it = 0; it < ITERS; it++) {
        const int s = it % STAGES;
        __syncthreads();            // all warps done reading stage (it+2)%3 (used at it-1)

        if (it + 2 < ITERS) issue(it + 2, (it + 2) % STAGES);

        MBAR_WAIT(sb + 16 * s, (it / STAGES) & 1);   // stage 'it' data resident

        const uint32_t aT = sb + 1024 + (uint32_t)s * STGB;
        const uint32_t bT = aT + ATILEB;
        const uint32_t aW = aT + (uint32_t)(wm * 64 + grp) * SROWB + qid * 8;
        const uint32_t bW = bT + (uint32_t)(wn * 64 + grp) * SROWB + qid * 8;

        #pragma unroll
        for (int ko = 0; ko < 2; ko++) {          // two k16 steps per chunk
            const uint32_t koff = ko * 64;        // 8 pairs * 8B
            uint32_t ah[4][4], al[4][4];
            #pragma unroll
            for (int mt = 0; mt < 4; mt++) {
                const uint32_t p = aW + (uint32_t)(mt * 16) * SROWB + koff;
                lds_v2(p,                  ah[mt][0], al[mt][0]);   // (r,   q)
                lds_v2(p + 8 * SROWB,      ah[mt][1], al[mt][1]);   // (r+8, q)
                lds_v2(p + 32,             ah[mt][2], al[mt][2]);   // (r,   q+4)
                lds_v2(p + 8 * SROWB + 32, ah[mt][3], al[mt][3]);   // (r+8, q+4)
            }
            // B in two halves of 4 nt to cap live registers
            #pragma unroll
            for (int nh = 0; nh < 2; nh++) {
                uint32_t bh[4][2], bl[4][2];
                #pragma unroll
                for (int nt = 0; nt < 4; nt++) {
                    const uint32_t p = bW + (uint32_t)(nh * 32 + nt * 8) * SROWB + koff;
                    lds_v2(p,      bh[nt][0], bl[nt][0]);
                    lds_v2(p + 32, bh[nt][1], bl[nt][1]);
                }
                // TERM-MAJOR bf16x3: 16 independent accs between chain steps.
                // Per-acc order stays hh, hl, lh => bit-identical results.
                #pragma unroll
                for (int mt = 0; mt < 4; mt++)
                    #pragma unroll
                    for (int nt = 0; nt < 4; nt++)
                        mma_bf16(acc[mt][nh * 4 + nt], ah[mt], bh[nt]);
                #pragma unroll
                for (int mt = 0; mt < 4; mt++)
                    #pragma unroll
                    for (int nt = 0; nt < 4; nt++)
                        mma_bf16(acc[mt][nh * 4 + nt], ah[mt], bl[nt]);
                #pragma unroll
                for (int mt = 0; mt < 4; mt++)
                    #pragma unroll
                    for (int nt = 0; nt < 4; nt++)
                        mma_bf16(acc[mt][nh * 4 + nt], al[mt], bh[nt]);
            }
        }
    }

    // ---------------- epilogue ----------------
    #pragma unroll
    for (int mt = 0; mt < 4; mt++) {
        #pragma unroll
        for (int half = 0; half < 2; half++) {
            const int gi = m0 + wm * 64 + mt * 16 + grp + half * 8;
            if (MODE == 0) {
                // scatter split Q / K / V^T into blocked tiles, with bias
                const int bb = gi >> 11;            // batch
                const int ni = gi & (SEQ - 1);      // token
                #pragma unroll
                for (int nt = 0; nt < 8; nt++) {
                    #pragma unroll
                    for (int e = 0; e < 2; e++) {
                        const int gj = n0 + wn * 64 + nt * 8 + qid * 2 + e;
                        float val = acc[mt][nt][half * 2 + e] + bias[gj];
                        unsigned short hu, lu;
                        split1(val, hu, lu);
                        const int which = gj % 3;
                        const int tt    = gj / 3;
                        const int h     = tt >> 8;
                        const int d     = tt & (HDIM - 1);
                        const int bh    = (bb << 3) + h;
                        if (which == 0) {
                            const int p = d >> 1, sl = d & 1;
                            unsigned short* w = (unsigned short*)(g_aq
                                + (size_t)bh * (16 * 8 * ATILEB)
                                + ((size_t)((ni >> 7) * 8 + (p >> 4)) * 128 + (ni & 127)) * SROWB
                                + (p & 15) * 8);
                            w[sl] = hu; w[2 + sl] = lu;
                        } else if (which == 1) {
                            const int p = d >> 1, sl = d & 1;
                            unsigned short* w = (unsigned short*)(g_bk
                                + (size_t)bh * (8 * 8 * BTILEB)
                                + ((size_t)((ni >> 8) * 8 + (p >> 4)) * 256 + (ni & 255)) * SROWB
                                + (p & 15) * 8);
                            w[sl] = hu; w[2 + sl] = lu;
                        } else {
                            const int p = ni >> 1, sl = ni & 1;
                            unsigned short* w = (unsigned short*)(g_bv
                                + (size_t)bh * (64 * BTILEB)
                                + ((size_t)(p >> 4) * 256 + d) * SROWB
                                + (p & 15) * 8);
                            w[sl] = hu; w[2 + sl] = lu;
                        }
                    }
                }
            } else if (MODE == 1) {
                // fp32 logits (flat)
                float* crow = g_s + (size_t)z * SEQ * SEQ
                            + (size_t)gi * SEQ + n0 + wn * 64 + qid * 2;
                #pragma unroll
                for (int nt = 0; nt < 8; nt++) {
                    float2 v;
                    v.x = acc[mt][nt][half * 2 + 0];
                    v.y = acc[mt][nt][half * 2 + 1];
                    *(float2*)(crow + nt * 8) = v;
                }
            } else if (MODE == 2) {
                // split O into blocked A-tiles for mode3
                const int orow = (z >> 3) * SEQ + gi;
                #pragma unroll
                for (int nt = 0; nt < 8; nt++) {
                    const int ec = (z & 7) * HDIM + n0 + wn * 64 + nt * 8 + qid * 2;
                    const int p = ec >> 1;
                    uint32_t hw, lw;
                    split2(acc[mt][nt][half * 2 + 0], acc[mt][nt][half * 2 + 1], hw, lw);
                    *(uint2*)(g_ao
                        + ((size_t)((orow >> 7) * 64 + (p >> 4)) * 128 + (orow & 127)) * SROWB
                        + (p & 15) * 8) = make_uint2(hw, lw);
                }
            } else {
                // fp32 output + bias
                float* crow = Cout + (size_t)gi * EMBD + n0 + wn * 64 + qid * 2;
                #pragma unroll
                for (int nt = 0; nt < 8; nt++) {
                    const int gj = n0 + wn * 64 + nt * 8 + qid * 2;
                    float2 v;
                    v.x = acc[mt][nt][half * 2 + 0] + bias[gj + 0];
                    v.y = acc[mt][nt][half * 2 + 1] + bias[gj + 1];
                    *(float2*)(crow + nt * 8) = v;
                }
            }
        }
    }
}

// ---------------------------------------------------------------------------
// Transpose + split weights: fp32 [K][N] -> blocked B-tiles (Tn=256, KCH=64)
// ---------------------------------------------------------------------------
__global__ __launch_bounds__(256)
void transpose_pack_k(const float* __restrict__ in, unsigned char* __restrict__ out,
                      int N)
{
    __shared__ float t[64][33];
    const int j0 = blockIdx.y * 32;     // output pair index base
    const int n0 = blockIdx.x * 32;
    const int x  = threadIdx.x & 31;
    const int y  = threadIdx.x >> 5;    // 0..7
    #pragma unroll
    for (int i = 0; i < 8; i++) {
        const int r = y + 8 * i;        // 0..63
        t[r][x] = in[(size_t)(2 * j0 + r) * N + n0 + x];
    }
    __syncthreads();
    #pragma unroll
    for (int i = 0; i < 4; i++) {
        const int n  = n0 + y + 8 * i;
        const int jp = j0 + x;
        uint32_t hw, lw;
        split2(t[2 * x][y + 8 * i], t[2 * x + 1][y + 8 * i], hw, lw);
        *(uint2*)(out
            + ((size_t)((n >> 8) * 64 + (jp >> 4)) * 256 + (n & 255)) * SROWB
            + (jp & 15) * 8) = make_uint2(hw, lw);
    }
}

// Split-copy of x into blocked A-tiles (Tm=128, KCH=64)
__global__ __launch_bounds__(256)
void splitx_k(const float2* __restrict__ in)
{
    const int i = blockIdx.x * blockDim.x + threadIdx.x;
    if (i < BN_ROWS * (EMBD / 2)) {
        const int m = i >> 10;          // row (EMBD/2 = 1024 pairs per row)
        const int p = i & 1023;         // pair index
        float2 v = in[i];
        uint32_t hw, lw;
        split2(v.x, v.y, hw, lw);
        *(uint2*)(g_ax
            + ((size_t)((m >> 7) * 64 + (p >> 4)) * 128 + (m & 127)) * SROWB
            + (p & 15) * 8) = make_uint2(hw, lw);
    }
}

// ---------------------------------------------------------------------------
// Row softmax over flat g_s, folds 1/sqrt(EMB), writes split P into blocked
// A-tiles for the P@V GEMM (Tm=128, KCH=64, per bh).
// ---------------------------------------------------------------------------
__global__ __launch_bounds__(256)
void softmax_k()
{
    constexpr float INV_SCALE = 0.02209708691207961f;   // 1/sqrt(2048)
    const int bh = blockIdx.x >> 11;
    const int q  = blockIdx.x & 2047;
    const float* p = g_s + (size_t)blockIdx.x * SEQ;
    const int t = threadIdx.x, w = t >> 5, l = t & 31;

    float2 v[4];
    float m = -3.0e38f;
    #pragma unroll
    for (int u = 0; u < 4; u++) {
        v[u] = ((const float2*)p)[t + 256 * u];
        m = fmaxf(m, fmaxf(v[u].x, v[u].y));
    }
    #pragma unroll
    for (int o = 16; o > 0; o >>= 1) m = fmaxf(m, __shfl_xor_sync(~0u, m, o));

    __shared__ float redm[8], reds[8];
    if (l == 0) redm[w] = m;
    __syncthreads();
    m = redm[0];
    #pragma unroll
    for (int i = 1; i < 8; i++) m = fmaxf(m, redm[i]);

    float s = 0.0f;
    #pragma unroll
    for (int u = 0; u < 4; u++) {
        v[u].x = __expf(v[u].x - m);
        v[u].y = __expf(v[u].y - m);
        s += v[u].x + v[u].y;
    }
    #pragma unroll
    for (int o = 16; o > 0; o >>= 1) s += __shfl_xor_sync(~0u, s, o);
    if (l == 0) reds[w] = s;
    __syncthreads();
    s = reds[0];
    #pragma unroll
    for (int i = 1; i < 8; i++) s += reds[i];

    const float r = INV_SCALE / s;
    unsigned char* obase = g_ap + (size_t)bh * (16 * 64 * ATILEB)
                         + (size_t)(q >> 7) * (64 * ATILEB)
                         + (size_t)(q & 127) * SROWB;
    #pragma unroll
    for (int u = 0; u < 4; u++) {
        const int kp = t + 256 * u;     // pair index over SEQ/2
        uint32_t hw, lw;
        split2(v[u].x * r, v[u].y * r, hw, lw);
        *(uint2*)(obase + (size_t)(kp >> 4) * ATILEB + (kp & 15) * 8) = make_uint2(hw, lw);
    }
}

// ---------------------------------------------------------------------------
extern "C" void kernel_launch(void* const* d_in, const int* in_sizes, int n_in,
                              void* d_out, int out_size)
{
    const float* x      = (const float*)d_in[0];
    const float* w_qkv  = (const float*)d_in[1];
    const float* b_qkv  = (const float*)d_in[2];
    const float* w_proj = (const float*)d_in[3];
    const float* b_proj = (const float*)d_in[4];
    float*       out    = (float*)d_out;

    cudaFuncSetAttribute(tc_gemm<0>, cudaFuncAttributeMaxDynamicSharedMemorySize, SMEM_BYTES);
    cudaFuncSetAttribute(tc_gemm<1>, cudaFuncAttributeMaxDynamicSharedMemorySize, SMEM_BYTES);
    cudaFuncSetAttribute(tc_gemm<2>, cudaFuncAttributeMaxDynamicSharedMemorySize, SMEM_BYTES);
    cudaFuncSetAttribute(tc_gemm<3>, cudaFuncAttributeMaxDynamicSharedMemorySize, SMEM_BYTES);

    unsigned char* gwq; unsigned char* gwp;
    cudaGetSymbolAddress((void**)&gwq, g_bqkv);
    cudaGetSymbolAddress((void**)&gwp, g_bpr);

    // 0) split x into A-tiles; transpose+split weights into B-tiles
    const int np = BN_ROWS * (EMBD / 2);
    splitx_k<<<(np + 255) / 256, 256>>>((const float2*)x);
    transpose_pack_k<<<dim3(QKV_N / 32, EMBD / 64), 256>>>(w_qkv,  gwq, QKV_N);
    transpose_pack_k<<<dim3(EMBD  / 32, EMBD / 64), 256>>>(w_proj, gwp, EMBD);

    // 1) QKV projection + de-interleave into split Q / K / V^T tiles
    tc_gemm<0><<<dim3(QKV_N / 256, BN_ROWS / 128, 1), NTHREADS, SMEM_BYTES>>>(b_qkv, nullptr);
    // 2) scores S = Q @ K^T per bh (fp32 flat out)
    tc_gemm<1><<<dim3(SEQ / 256, SEQ / 128, NBH), NTHREADS, SMEM_BYTES>>>(nullptr, nullptr);
    // 3) softmax (folds 1/sqrt(EMB)) -> split P tiles
    softmax_k<<<NBH * SEQ, 256>>>();
    // 4) O = P @ V per bh -> split O tiles ([b, n, h*d] order)
    tc_gemm<2><<<dim3(HDIM / 256, SEQ / 128, NBH), NTHREADS, SMEM_BYTES>>>(nullptr, nullptr);
    // 5) final projection + bias (fp32 out)
    tc_gemm<3><<<dim3(EMBD / 256, BN_ROWS / 128, 1), NTHREADS, SMEM_BYTES>>>(b_proj, out);
}

// round 17
// speedup vs baseline: 1.2009x; 1.0847x over previous
#include <cuda_runtime.h>
#include <cstdint>

// ---------------------------------------------------------------------------
// Problem constants
// ---------------------------------------------------------------------------
#define EMBD   2048
#define HEADS  8
#define HDIM   256
#define BATCH  2
#define SEQ    2048
#define BN_ROWS (BATCH*SEQ)      // 4096
#define QKV_N  (3*EMBD)          // 6144
#define NBH    (BATCH*HEADS)     // 16

// ---------------------------------------------------------------------------
// Blocked-tile operand format (UNCHANGED from R15/R16 producers):
// padded 160B rows; A-tile = 128x160B = 20480B, B-tile = 256x160B = 40960B,
// contiguous per (tile, k-chunk). A 128-row half of a B-tile is contiguous
// within each chunk, so a 128-wide CTA grabs it with one bulk copy + offset.
// Element format: bf16 hi/lo pairs, uint2{hi(k),hi(k+1), lo(k),lo(k+1)}.
// ---------------------------------------------------------------------------
#define SROWB   160
#define ATILEB  20480
#define BTILEB  40960
#define HBTILEB 20480                   // 128-row half of a B tile per chunk
#define STGB    (ATILEB + HBTILEB)      // 40960 per stage (A + B-half)
#define STAGES  2
#define SMEM_BYTES (1024 + STAGES*STGB) // 82944  -> 2 CTAs/SM
#define NTHREADS 128

// ---------------------------------------------------------------------------
// Device scratch (blocked-tile operand buffers + flat logits) — unchanged
// ---------------------------------------------------------------------------
__device__ __align__(1024) unsigned char g_ax  [(size_t)32*64*ATILEB];      // x       A-tiles (mode0)
__device__ __align__(1024) unsigned char g_bqkv[(size_t)24*64*BTILEB];      // w_qkv^T B-tiles (mode0)
__device__ __align__(1024) unsigned char g_aq  [(size_t)16*16*8*ATILEB];    // Q       A-tiles (mode1, per bh)
__device__ __align__(1024) unsigned char g_bk  [(size_t)16*8*8*BTILEB];     // K       B-tiles (mode1, per bh)
__device__ __align__(1024) unsigned char g_ap  [(size_t)16*16*64*ATILEB];   // P       A-tiles (mode2, per bh)
__device__ __align__(1024) unsigned char g_bv  [(size_t)16*64*BTILEB];      // V^T     B-tiles (mode2, per bh)
__device__ __align__(1024) unsigned char g_ao  [(size_t)32*64*ATILEB];      // O       A-tiles (mode3)
__device__ __align__(1024) unsigned char g_bpr [(size_t)8*64*BTILEB];       // w_proj^T B-tiles (mode3)
__device__ __align__(1024) float g_s [(size_t)NBH*SEQ*SEQ];                 // logits fp32 (flat)

// ---------------------------------------------------------------------------
// Helpers
// ---------------------------------------------------------------------------
__device__ __forceinline__ uint32_t smem_u32(const void* p) {
    uint32_t a;
    asm("{ .reg .u64 t; cvta.to.shared.u64 t, %1; cvt.u32.u64 %0, t; }"
        : "=r"(a) : "l"(p));
    return a;
}

__device__ __forceinline__ uint32_t pack_bf16x2(float x0, float x1) {
    uint32_t w;
    asm("cvt.rn.bf16x2.f32 %0, %1, %2;" : "=r"(w) : "f"(x1), "f"(x0));
    return w;
}

__device__ __forceinline__ void split2(float x0, float x1, uint32_t& hw, uint32_t& lw) {
    hw = pack_bf16x2(x0, x1);
    float h0 = __uint_as_float(hw << 16);
    float h1 = __uint_as_float(hw & 0xffff0000u);
    lw = pack_bf16x2(x0 - h0, x1 - h1);
}

__device__ __forceinline__ void split1(float v, unsigned short& hu, unsigned short& lu) {
    uint32_t hw = pack_bf16x2(v, 0.0f);
    float hf = __uint_as_float(hw << 16);
    uint32_t lw = pack_bf16x2(v - hf, 0.0f);
    hu = (unsigned short)(hw & 0xffffu);
    lu = (unsigned short)(lw & 0xffffu);
}

__device__ __forceinline__ void mma_bf16(float* c, const uint32_t* a, const uint32_t* b) {
    asm volatile(
        "mma.sync.aligned.m16n8k16.row.col.f32.bf16.bf16.f32 "
        "{%0,%1,%2,%3}, {%4,%5,%6,%7}, {%8,%9}, {%0,%1,%2,%3};"
        : "+f"(c[0]), "+f"(c[1]), "+f"(c[2]), "+f"(c[3])
        : "r"(a[0]), "r"(a[1]), "r"(a[2]), "r"(a[3]), "r"(b[0]), "r"(b[1]));
}

__device__ __forceinline__ void lds_v2(uint32_t addr, uint32_t& h, uint32_t& l) {
    asm volatile("ld.shared.v2.b32 {%0, %1}, [%2];" : "=r"(h), "=r"(l) : "r"(addr));
}

// Bulk async copy gmem -> smem with mbarrier transaction completion (sm_90 base)
__device__ __forceinline__ void bulk_g2s(uint32_t s, const void* g, uint32_t bytes, uint32_t mb) {
    asm volatile(
        "cp.async.bulk.shared::cluster.global.mbarrier::complete_tx::bytes "
        "[%0], [%1], %2, [%3];"
        :: "r"(s), "l"(g), "r"(bytes), "r"(mb) : "memory");
}

#define MBAR_INIT(a, cnt) \
    asm volatile("mbarrier.init.shared.b64 [%0], %1;" :: "r"(a), "r"(cnt) : "memory")

#define MBAR_EXPECT_TX(a, bytes) \
    asm volatile("mbarrier.arrive.expect_tx.shared.b64 _, [%0], %1;" \
                 :: "r"(a), "r"((uint32_t)(bytes)) : "memory")

#define MBAR_WAIT(a, ph) do { \
    uint32_t _m = (a); uint32_t _p = (ph); uint32_t _d; \
    asm volatile("{\n\t.reg .pred p;\n\t" \
        "mbarrier.try_wait.parity.acquire.cta.shared::cta.b64 p, [%1], %2;\n\t" \
        "selp.b32 %0, 1, 0, p;\n\t}" : "=r"(_d) : "r"(_m), "r"(_p) : "memory"); \
    if (!_d) { \
        asm volatile("{\n\t.reg .pred P1;\n\t" \
            "WL_%=:\n\t" \
            "mbarrier.try_wait.parity.acquire.cta.shared::cta.b64 P1, [%0], %1, 0x989680;\n\t" \
            "@P1 bra.uni WD_%=;\n\t" \
            "bra.uni WL_%=;\n\t" \
            "WD_%=:\n\t}" :: "r"(_m), "r"(_p) : "memory"); \
    } } while (0)

// ---------------------------------------------------------------------------
// bf16x3 HMMA GEMM: CTA tile 128x128, 4 warps (2x2, 64x64 warp tile),
// mma m16n8k16, 2-stage bulk-copy pipeline, 2 CTAs/SM so one CTA's
// barrier/mbar bubbles are covered by the other CTA's compute.
// MODE 0: x @ wqkvT^T     -> scatter split Q / K / V^T tiles (+bias)
// MODE 1: Q @ K^T per bh  -> g_s (fp32 flat)
// MODE 2: P @ V per bh    -> O tiles ([b,n,h*d] order)
// MODE 3: o @ wprojT^T    -> out (fp32, +bias)
// ---------------------------------------------------------------------------
template <int MODE>
__global__ __launch_bounds__(NTHREADS, 2)
void tc_gemm(const float* __restrict__ bias, float* __restrict__ Cout)
{
    constexpr int ITERS = (MODE == 1) ? 8 : 64;   // k-chunks (K/32)

    const int z     = blockIdx.z;
    const int m0    = blockIdx.y * 128;
    const int n0    = blockIdx.x * 128;
    const int nTile = blockIdx.x >> 1;            // 256-row B-tile index
    const int nHalf = blockIdx.x & 1;             // which 128-row half

    const unsigned char* Abase; const unsigned char* Bbase;
    if (MODE == 0)      { Abase = g_ax   + (size_t)blockIdx.y * 64 * ATILEB;
                          Bbase = g_bqkv + (size_t)nTile * 64 * BTILEB; }
    else if (MODE == 1) { Abase = g_aq + ((size_t)z * 16 + blockIdx.y) * 8 * ATILEB;
                          Bbase = g_bk + ((size_t)z * 8 + nTile) * 8 * BTILEB; }
    else if (MODE == 2) { Abase = g_ap + ((size_t)z * 16 + blockIdx.y) * 64 * ATILEB;
                          Bbase = g_bv + (size_t)z * 64 * BTILEB; }           // nTile==0
    else                { Abase = g_ao  + (size_t)blockIdx.y * 64 * ATILEB;
                          Bbase = g_bpr + (size_t)nTile * 64 * BTILEB; }
    Bbase += (size_t)nHalf * 128 * SROWB;          // 128-row half within each chunk

    extern __shared__ __align__(128) char smem[];
    const uint32_t sb = smem_u32(smem);

    const int tid  = threadIdx.x;
    const int wid  = tid >> 5;
    const int lane = tid & 31;
    const int wm   = wid & 1;          // warp row (2) -> 64 rows
    const int wn   = wid >> 1;         // warp col (2) -> 64 cols
    const int grp  = lane >> 2;        // 0..7
    const int qid  = lane & 3;         // 0..3

    if (tid == 0) {
        MBAR_INIT(sb + 0, 1);
        MBAR_INIT(sb + 16, 1);
    }
    __syncthreads();

    auto issue = [&](int it, int s) {
        const uint32_t mb = sb + 16 * s;
        const uint32_t dA = sb + 1024 + (uint32_t)s * STGB;
        MBAR_EXPECT_TX(mb, STGB);
        bulk_g2s(dA, Abase + (size_t)it * ATILEB, ATILEB, mb);
        bulk_g2s(dA + ATILEB, Bbase + (size_t)it * BTILEB, HBTILEB, mb);
    };

    if (tid == 0) { issue(0, 0); issue(1, 1); }

    float acc[4][8][4];
    #pragma unroll
    for (int mt = 0; mt < 4; mt++)
        #pragma unroll
        for (int nt = 0; nt < 8; nt++)
            #pragma unroll
            for (int e = 0; e < 4; e++) acc[mt][nt][e] = 0.0f;

    for (int it = 0; it < ITERS; it++) {
        const int s = it & 1;
        MBAR_WAIT(sb + 16 * s, (it >> 1) & 1);    // stage s data resident

        const uint32_t aT = sb + 1024 + (uint32_t)s * STGB;
        const uint32_t bT = aT + ATILEB;
        const uint32_t aW = aT + (uint32_t)(wm * 64 + grp) * SROWB + qid * 8;
        const uint32_t bW = bT + (uint32_t)(wn * 64 + grp) * SROWB + qid * 8;

        #pragma unroll
        for (int ko = 0; ko < 2; ko++) {          // two k16 steps per chunk
            const uint32_t koff = ko * 64;        // 8 pairs * 8B
            uint32_t ah[4][4], al[4][4];
            #pragma unroll
            for (int mt = 0; mt < 4; mt++) {
                const uint32_t p = aW + (uint32_t)(mt * 16) * SROWB + koff;
                lds_v2(p,                  ah[mt][0], al[mt][0]);   // (r,   q)
                lds_v2(p + 8 * SROWB,      ah[mt][1], al[mt][1]);   // (r+8, q)
                lds_v2(p + 32,             ah[mt][2], al[mt][2]);   // (r,   q+4)
                lds_v2(p + 8 * SROWB + 32, ah[mt][3], al[mt][3]);   // (r+8, q+4)
            }
            // B in two halves of 4 nt to cap live registers
            #pragma unroll
            for (int nh = 0; nh < 2; nh++) {
                uint32_t bh[4][2], bl[4][2];
                #pragma unroll
                for (int nt = 0; nt < 4; nt++) {
                    const uint32_t p = bW + (uint32_t)(nh * 32 + nt * 8) * SROWB + koff;
                    lds_v2(p,      bh[nt][0], bl[nt][0]);
                    lds_v2(p + 32, bh[nt][1], bl[nt][1]);
                }
                // term-major bf16x3: hh then hl then lh (per-acc order preserved)
                #pragma unroll
                for (int mt = 0; mt < 4; mt++)
                    #pragma unroll
                    for (int nt = 0; nt < 4; nt++)
                        mma_bf16(acc[mt][nh * 4 + nt], ah[mt], bh[nt]);
                #pragma unroll
                for (int mt = 0; mt < 4; mt++)
                    #pragma unroll
                    for (int nt = 0; nt < 4; nt++)
                        mma_bf16(acc[mt][nh * 4 + nt], ah[mt], bl[nt]);
                #pragma unroll
                for (int mt = 0; mt < 4; mt++)
                    #pragma unroll
                    for (int nt = 0; nt < 4; nt++)
                        mma_bf16(acc[mt][nh * 4 + nt], al[mt], bh[nt]);
            }
        }

        __syncthreads();                         // all warps done reading stage s
        if (tid == 0 && it + 2 < ITERS) issue(it + 2, s);   // refill s; overlaps next iter
    }

    // ---------------- epilogue ----------------
    #pragma unroll
    for (int mt = 0; mt < 4; mt++) {
        #pragma unroll
        for (int half = 0; half < 2; half++) {
            const int gi = m0 + wm * 64 + mt * 16 + grp + half * 8;
            if (MODE == 0) {
                // scatter split Q / K / V^T into blocked tiles, with bias
                const int bb = gi >> 11;            // batch
                const int ni = gi & (SEQ - 1);      // token
                #pragma unroll
                for (int nt = 0; nt < 8; nt++) {
                    #pragma unroll
                    for (int e = 0; e < 2; e++) {
                        const int gj = n0 + wn * 64 + nt * 8 + qid * 2 + e;
                        float val = acc[mt][nt][half * 2 + e] + bias[gj];
                        unsigned short hu, lu;
                        split1(val, hu, lu);
                        const int which = gj % 3;
                        const int tt    = gj / 3;
                        const int h     = tt >> 8;
                        const int d     = tt & (HDIM - 1);
                        const int bh    = (bb << 3) + h;
                        if (which == 0) {
                            const int p = d >> 1, sl = d & 1;
                            unsigned short* w = (unsigned short*)(g_aq
                                + (size_t)bh * (16 * 8 * ATILEB)
                                + ((size_t)((ni >> 7) * 8 + (p >> 4)) * 128 + (ni & 127)) * SROWB
                                + (p & 15) * 8);
                            w[sl] = hu; w[2 + sl] = lu;
                        } else if (which == 1) {
                            const int p = d >> 1, sl = d & 1;
                            unsigned short* w = (unsigned short*)(g_bk
                                + (size_t)bh * (8 * 8 * BTILEB)
                                + ((size_t)((ni >> 8) * 8 + (p >> 4)) * 256 + (ni & 255)) * SROWB
                                + (p & 15) * 8);
                            w[sl] = hu; w[2 + sl] = lu;
                        } else {
                            const int p = ni >> 1, sl = ni & 1;
                            unsigned short* w = (unsigned short*)(g_bv
                                + (size_t)bh * (64 * BTILEB)
                                + ((size_t)(p >> 4) * 256 + d) * SROWB
                                + (p & 15) * 8);
                            w[sl] = hu; w[2 + sl] = lu;
                        }
                    }
                }
            } else if (MODE == 1) {
                // fp32 logits (flat)
                float* crow = g_s + (size_t)z * SEQ * SEQ
                            + (size_t)gi * SEQ + n0 + wn * 64 + qid * 2;
                #pragma unroll
                for (int nt = 0; nt < 8; nt++) {
                    float2 v;
                    v.x = acc[mt][nt][half * 2 + 0];
                    v.y = acc[mt][nt][half * 2 + 1];
                    *(float2*)(crow + nt * 8) = v;
                }
            } else if (MODE == 2) {
                // split O into blocked A-tiles for mode3
                const int orow = (z >> 3) * SEQ + gi;
                #pragma unroll
                for (int nt = 0; nt < 8; nt++) {
                    const int ec = (z & 7) * HDIM + n0 + wn * 64 + nt * 8 + qid * 2;
                    const int p = ec >> 1;
                    uint32_t hw, lw;
                    split2(acc[mt][nt][half * 2 + 0], acc[mt][nt][half * 2 + 1], hw, lw);
                    *(uint2*)(g_ao
                        + ((size_t)((orow >> 7) * 64 + (p >> 4)) * 128 + (orow & 127)) * SROWB
                        + (p & 15) * 8) = make_uint2(hw, lw);
                }
            } else {
                // fp32 output + bias
                float* crow = Cout + (size_t)gi * EMBD + n0 + wn * 64 + qid * 2;
                #pragma unroll
                for (int nt = 0; nt < 8; nt++) {
                    const int gj = n0 + wn * 64 + nt * 8 + qid * 2;
                    float2 v;
                    v.x = acc[mt][nt][half * 2 + 0] + bias[gj + 0];
                    v.y = acc[mt][nt][half * 2 + 1] + bias[gj + 1];
                    *(float2*)(crow + nt * 8) = v;
                }
            }
        }
    }
}

// ---------------------------------------------------------------------------
// Transpose + split weights: fp32 [K][N] -> blocked B-tiles (Tn=256, KCH=64)
// ---------------------------------------------------------------------------
__global__ __launch_bounds__(256)
void transpose_pack_k(const float* __restrict__ in, unsigned char* __restrict__ out,
                      int N)
{
    __shared__ float t[64][33];
    const int j0 = blockIdx.y * 32;     // output pair index base
    const int n0 = blockIdx.x * 32;
    const int x  = threadIdx.x & 31;
    const int y  = threadIdx.x >> 5;    // 0..7
    #pragma unroll
    for (int i = 0; i < 8; i++) {
        const int r = y + 8 * i;        // 0..63
        t[r][x] = in[(size_t)(2 * j0 + r) * N + n0 + x];
    }
    __syncthreads();
    #pragma unroll
    for (int i = 0; i < 4; i++) {
        const int n  = n0 + y + 8 * i;
        const int jp = j0 + x;
        uint32_t hw, lw;
        split2(t[2 * x][y + 8 * i], t[2 * x + 1][y + 8 * i], hw, lw);
        *(uint2*)(out
            + ((size_t)((n >> 8) * 64 + (jp >> 4)) * 256 + (n & 255)) * SROWB
            + (jp & 15) * 8) = make_uint2(hw, lw);
    }
}

// Split-copy of x into blocked A-tiles (Tm=128, KCH=64)
__global__ __launch_bounds__(256)
void splitx_k(const float2* __restrict__ in)
{
    const int i = blockIdx.x * blockDim.x + threadIdx.x;
    if (i < BN_ROWS * (EMBD / 2)) {
        const int m = i >> 10;          // row (EMBD/2 = 1024 pairs per row)
        const int p = i & 1023;         // pair index
        float2 v = in[i];
        uint32_t hw, lw;
        split2(v.x, v.y, hw, lw);
        *(uint2*)(g_ax
            + ((size_t)((m >> 7) * 64 + (p >> 4)) * 128 + (m & 127)) * SROWB
            + (p & 15) * 8) = make_uint2(hw, lw);
    }
}

// ---------------------------------------------------------------------------
// Row softmax over flat g_s, folds 1/sqrt(EMB), writes split P into blocked
// A-tiles for the P@V GEMM (Tm=128, KCH=64, per bh).
// ---------------------------------------------------------------------------
__global__ __launch_bounds__(256)
void softmax_k()
{
    constexpr float INV_SCALE = 0.02209708691207961f;   // 1/sqrt(2048)
    const int bh = blockIdx.x >> 11;
    const int q  = blockIdx.x & 2047;
    const float* p = g_s + (size_t)blockIdx.x * SEQ;
    const int t = threadIdx.x, w = t >> 5, l = t & 31;

    float2 v[4];
    float m = -3.0e38f;
    #pragma unroll
    for (int u = 0; u < 4; u++) {
        v[u] = ((const float2*)p)[t + 256 * u];
        m = fmaxf(m, fmaxf(v[u].x, v[u].y));
    }
    #pragma unroll
    for (int o = 16; o > 0; o >>= 1) m = fmaxf(m, __shfl_xor_sync(~0u, m, o));

    __shared__ float redm[8], reds[8];
    if (l == 0) redm[w] = m;
    __syncthreads();
    m = redm[0];
    #pragma unroll
    for (int i = 1; i < 8; i++) m = fmaxf(m, redm[i]);

    float s = 0.0f;
    #pragma unroll
    for (int u = 0; u < 4; u++) {
        v[u].x = __expf(v[u].x - m);
        v[u].y = __expf(v[u].y - m);
        s += v[u].x + v[u].y;
    }
    #pragma unroll
    for (int o = 16; o > 0; o >>= 1) s += __shfl_xor_sync(~0u, s, o);
    if (l == 0) reds[w] = s;
    __syncthreads();
    s = reds[0];
    #pragma unroll
    for (int i = 1; i < 8; i++) s += reds[i];

    const float r = INV_SCALE / s;
    unsigned char* obase = g_ap + (size_t)bh * (16 * 64 * ATILEB)
                         + (size_t)(q >> 7) * (64 * ATILEB)
                         + (size_t)(q & 127) * SROWB;
    #pragma unroll
    for (int u = 0; u < 4; u++) {
        const int kp = t + 256 * u;     // pair index over SEQ/2
        uint32_t hw, lw;
        split2(v[u].x * r, v[u].y * r, hw, lw);
        *(uint2*)(obase + (size_t)(kp >> 4) * ATILEB + (kp & 15) * 8) = make_uint2(hw, lw);
    }
}

// ---------------------------------------------------------------------------
extern "C" void kernel_launch(void* const* d_in, const int* in_sizes, int n_in,
                              void* d_out, int out_size)
{
    const float* x      = (const float*)d_in[0];
    const float* w_qkv  = (const float*)d_in[1];
    const float* b_qkv  = (const float*)d_in[2];
    const float* w_proj = (const float*)d_in[3];
    const float* b_proj = (const float*)d_in[4];
    float*       out    = (float*)d_out;

    cudaFuncSetAttribute(tc_gemm<0>, cudaFuncAttributeMaxDynamicSharedMemorySize, SMEM_BYTES);
    cudaFuncSetAttribute(tc_gemm<1>, cudaFuncAttributeMaxDynamicSharedMemorySize, SMEM_BYTES);
    cudaFuncSetAttribute(tc_gemm<2>, cudaFuncAttributeMaxDynamicSharedMemorySize, SMEM_BYTES);
    cudaFuncSetAttribute(tc_gemm<3>, cudaFuncAttributeMaxDynamicSharedMemorySize, SMEM_BYTES);

    unsigned char* gwq; unsigned char* gwp;
    cudaGetSymbolAddress((void**)&gwq, g_bqkv);
    cudaGetSymbolAddress((void**)&gwp, g_bpr);

    // 0) split x into A-tiles; transpose+split weights into B-tiles
    const int np = BN_ROWS * (EMBD / 2);
    splitx_k<<<(np + 255) / 256, 256>>>((const float2*)x);
    transpose_pack_k<<<dim3(QKV_N / 32, EMBD / 64), 256>>>(w_qkv,  gwq, QKV_N);
    transpose_pack_k<<<dim3(EMBD  / 32, EMBD / 64), 256>>>(w_proj, gwp, EMBD);

    // 1) QKV projection + de-interleave into split Q / K / V^T tiles
    tc_gemm<0><<<dim3(QKV_N / 128, BN_ROWS / 128, 1), NTHREADS, SMEM_BYTES>>>(b_qkv, nullptr);
    // 2) scores S = Q @ K^T per bh (fp32 flat out)
    tc_gemm<1><<<dim3(SEQ / 128, SEQ / 128, NBH), NTHREADS, SMEM_BYTES>>>(nullptr, nullptr);
    // 3) softmax (folds 1/sqrt(EMB)) -> split P tiles
    softmax_k<<<NBH * SEQ, 256>>>();
    // 4) O = P @ V per bh -> split O tiles ([b, n, h*d] order)
    tc_gemm<2><<<dim3(HDIM / 128, SEQ / 128, NBH), NTHREADS, SMEM_BYTES>>>(nullptr, nullptr);
    // 5) final projection + bias (fp32 out)
    tc_gemm<3><<<dim3(EMBD / 128, BN_ROWS / 128, 1), NTHREADS, SMEM_BYTES>>>(b_proj, out);
}